// round 3
// baseline (speedup 1.0000x reference)
#include <cuda_runtime.h>
#include <math.h>
#include <stdint.h>

// Problem constants
#define BB 4
#define CC 512
#define HH 128
#define WW 128
#define NN (HH*WW)          // 16384
#define CQ 64
#define OQK 128             // fused q(64) + k(64)

// ---------------- scratch (device globals; no allocation allowed) -----------
__device__ float g_qk[(size_t)BB*NN*OQK];       //  qk_t[b][n][0..63]=q, [64..127]=k
__device__ float g_v [(size_t)BB*NN*CC];        //  v_t[b][n][c]
__device__ float g_oH[(size_t)BB*NN*CC];        //  oH[((b*W+w)*H+h)*C + c]
__device__ float g_oW[(size_t)BB*NN*CC];        //  oW[((b*H+h)*W+w)*C + c]
__device__ float g_mH[(size_t)BB*NN];
__device__ float g_sH[(size_t)BB*NN];
__device__ float g_mW[(size_t)BB*NN];
__device__ float g_sW[(size_t)BB*NN];
__device__ float g_Wqk[OQK*CC];
__device__ float g_bqk[OQK];

// ---------------- tf32 mma helpers ------------------------------------------
__device__ __forceinline__ uint32_t f2tf(float f) {
    uint32_t u;
    asm("cvt.rna.tf32.f32 %0, %1;" : "=r"(u) : "f"(f));
    return u;
}

__device__ __forceinline__ void mma_tf32(float c[4], const uint32_t a[4], const uint32_t b[2]) {
    asm volatile(
        "mma.sync.aligned.m16n8k8.row.col.f32.tf32.tf32.f32 "
        "{%0,%1,%2,%3}, {%4,%5,%6,%7}, {%8,%9}, {%0,%1,%2,%3};"
        : "+f"(c[0]), "+f"(c[1]), "+f"(c[2]), "+f"(c[3])
        : "r"(a[0]), "r"(a[1]), "r"(a[2]), "r"(a[3]), "r"(b[0]), "r"(b[1]));
}

// ---------------- pack Wq,Wk -> combined ------------------------------------
__global__ void pack_wqk(const float* __restrict__ Wq, const float* __restrict__ bq,
                         const float* __restrict__ Wk, const float* __restrict__ bk)
{
    int i = blockIdx.x * blockDim.x + threadIdx.x;
    if (i < CQ*CC) {
        g_Wqk[i]          = Wq[i];
        g_Wqk[CQ*CC + i]  = Wk[i];
    }
    if (i < CQ) { g_bqk[i] = bq[i]; g_bqk[CQ + i] = bk[i]; }
}

// ---------------- TC GEMM (double-buffered): out_t[b][n][o] -----------------
#define AS_STRIDE 136
#define BS_STRIDE 36
#define SMEM_GEMM ((2*32*AS_STRIDE + 2*128*BS_STRIDE) * 4)

__global__ __launch_bounds__(256)
void gemm_qkv_tc(const float* __restrict__ X, const float* __restrict__ Wp,
                 const float* __restrict__ bp, int mode)
{
    extern __shared__ uint32_t smem_u[];
    uint32_t* As = smem_u;                    // [2][32][136]  (k, m)
    uint32_t* Bs = smem_u + 2*32*AS_STRIDE;   // [2][128][36]  (o, k)

    const int O = mode ? CC : OQK;
    const float* Wm   = mode ? Wp : g_Wqk;
    const float* bias = mode ? bp : g_bqk;
    float* outp       = mode ? g_v : g_qk;

    const int b  = blockIdx.z;
    const int n0 = blockIdx.y * 128;
    const int o0 = blockIdx.x * 128;

    const int tid  = threadIdx.x;
    const int warp = tid >> 5, lane = tid & 31;
    const int g = lane >> 2, tig = lane & 3;
    const int wm = warp >> 2, wn = warp & 3;

    const float* Xp = X + (size_t)b*CC*NN + n0;
    const float* Wb = Wm + (size_t)o0*CC;

    const int col4 = tid & 31, krowA = tid >> 5;
    const int orow = tid >> 1, kcB = (tid & 1) * 16;

    float4 ar[4], br[4];
    #pragma unroll
    for (int it = 0; it < 4; it++) {
        ar[it] = *(const float4*)(Xp + (size_t)(krowA + it*8)*NN + col4*4);
        br[it] = *(const float4*)(Wb + (size_t)orow*CC + kcB + it*4);
    }
    {
        #pragma unroll
        for (int it = 0; it < 4; it++) {
            uint32_t* d = As + (krowA + it*8)*AS_STRIDE + col4*4;
            d[0]=f2tf(ar[it].x); d[1]=f2tf(ar[it].y); d[2]=f2tf(ar[it].z); d[3]=f2tf(ar[it].w);
            uint32_t* e = Bs + orow*BS_STRIDE + kcB + it*4;
            e[0]=f2tf(br[it].x); e[1]=f2tf(br[it].y); e[2]=f2tf(br[it].z); e[3]=f2tf(br[it].w);
        }
    }
    __syncthreads();

    float acc[4][4][4];
    #pragma unroll
    for (int i = 0; i < 4; i++)
        #pragma unroll
        for (int j = 0; j < 4; j++)
            #pragma unroll
            for (int r = 0; r < 4; r++) acc[i][j][r] = 0.f;

    for (int t = 0; t < 16; t++) {
        const int cur = t & 1;
        if (t < 15) {
            const int c1 = (t+1)*32;
            #pragma unroll
            for (int it = 0; it < 4; it++) {
                ar[it] = *(const float4*)(Xp + (size_t)(c1 + krowA + it*8)*NN + col4*4);
                br[it] = *(const float4*)(Wb + (size_t)orow*CC + c1 + kcB + it*4);
            }
        }
        const uint32_t* Ac = As + cur*32*AS_STRIDE;
        const uint32_t* Bc = Bs + cur*128*BS_STRIDE;
        #pragma unroll
        for (int k8 = 0; k8 < 32; k8 += 8) {
            uint32_t af[4][4], bf[4][2];
            #pragma unroll
            for (int mt = 0; mt < 4; mt++) {
                const int rb = wm*64 + mt*16;
                af[mt][0] = Ac[(k8+tig  )*AS_STRIDE + rb + g];
                af[mt][1] = Ac[(k8+tig  )*AS_STRIDE + rb + g + 8];
                af[mt][2] = Ac[(k8+tig+4)*AS_STRIDE + rb + g];
                af[mt][3] = Ac[(k8+tig+4)*AS_STRIDE + rb + g + 8];
            }
            #pragma unroll
            for (int nt = 0; nt < 4; nt++) {
                const int cb = wn*32 + nt*8 + g;
                bf[nt][0] = Bc[cb*BS_STRIDE + k8 + tig];
                bf[nt][1] = Bc[cb*BS_STRIDE + k8 + tig + 4];
            }
            #pragma unroll
            for (int mt = 0; mt < 4; mt++)
                #pragma unroll
                for (int nt = 0; nt < 4; nt++)
                    mma_tf32(acc[mt][nt], af[mt], bf[nt]);
        }
        if (t < 15) {
            uint32_t* Ab = As + (cur^1)*32*AS_STRIDE;
            uint32_t* Bb = Bs + (cur^1)*128*BS_STRIDE;
            #pragma unroll
            for (int it = 0; it < 4; it++) {
                uint32_t* d = Ab + (krowA + it*8)*AS_STRIDE + col4*4;
                d[0]=f2tf(ar[it].x); d[1]=f2tf(ar[it].y); d[2]=f2tf(ar[it].z); d[3]=f2tf(ar[it].w);
                uint32_t* e = Bb + orow*BS_STRIDE + kcB + it*4;
                e[0]=f2tf(br[it].x); e[1]=f2tf(br[it].y); e[2]=f2tf(br[it].z); e[3]=f2tf(br[it].w);
            }
        }
        __syncthreads();
    }

    #pragma unroll
    for (int mt = 0; mt < 4; mt++) {
        int row = n0 + wm*64 + mt*16 + g;
        #pragma unroll
        for (int nt = 0; nt < 4; nt++) {
            int col = o0 + wn*32 + nt*8 + tig*2;
            float b0 = bias[col], b1 = bias[col + 1];
            size_t base0 = ((size_t)b * NN + row) * O + col;
            size_t base1 = base0 + (size_t)8 * O;
            *(float2*)(outp + base0) = make_float2(acc[mt][nt][0] + b0, acc[mt][nt][1] + b1);
            *(float2*)(outp + base1) = make_float2(acc[mt][nt][2] + b0, acc[mt][nt][3] + b1);
        }
    }
}

// ---------------- shared E-compute helpers (fp32, identical in stats & out) --
#define QK_STRIDE 65

__device__ __forceinline__ void load_qk_tiles(const float* __restrict__ base, size_t rstride,
                                              float* Qs, float* Ks, int tid)
{
    const int row = tid >> 1, half = tid & 1;
    const float* src = base + (size_t)row * rstride + half*32;
    float* qd = Qs + row*QK_STRIDE + half*32;
    float* kd = Ks + row*QK_STRIDE + half*32;
    #pragma unroll
    for (int i = 0; i < 8; i++) {
        float4 q4 = *(const float4*)(src + i*4);
        float4 k4 = *(const float4*)(src + 64 + i*4);
        qd[i*4+0]=q4.x; qd[i*4+1]=q4.y; qd[i*4+2]=q4.z; qd[i*4+3]=q4.w;
        kd[i*4+0]=k4.x; kd[i*4+1]=k4.y; kd[i*4+2]=k4.z; kd[i*4+3]=k4.w;
    }
}

__device__ __forceinline__ void compute_E(const float* Qs, const float* Ks,
                                          float acc[8][8], int tx, int ty)
{
    #pragma unroll
    for (int i = 0; i < 8; i++)
        #pragma unroll
        for (int j = 0; j < 8; j++) acc[i][j] = 0.f;
    #pragma unroll 8
    for (int c = 0; c < 64; c++) {
        float a[8], bb[8];
        #pragma unroll
        for (int i = 0; i < 8; i++) a[i]  = Qs[(ty + 16*i)*QK_STRIDE + c];
        #pragma unroll
        for (int j = 0; j < 8; j++) bb[j] = Ks[(tx + 16*j)*QK_STRIDE + c];
        #pragma unroll
        for (int i = 0; i < 8; i++)
            #pragma unroll
            for (int j = 0; j < 8; j++) acc[i][j] += a[i] * bb[j];
    }
}

// ---------------- stats: per-row (m, s) of eH / eW ---------------------------
#define SMEM_STATS (2*128*QK_STRIDE*4)

__global__ __launch_bounds__(256)
void stats_kernel(int isH)
{
    extern __shared__ float sm_f[];
    float* Qs = sm_f;                   // [128][65]
    float* Ks = sm_f + 128*QK_STRIDE;

    const int bz = blockIdx.x;
    const int b = bz >> 7, f = bz & 127;
    const int tid = threadIdx.x;
    const int tx = tid & 15, ty = tid >> 4;

    const float* base = g_qk + ((size_t)b*NN + (size_t)(isH ? f : f*WW)) * OQK;
    const size_t rstride = (size_t)(isH ? WW : 1) * OQK;
    load_qk_tiles(base, rstride, Qs, Ks, tid);
    __syncthreads();

    float acc[8][8];
    compute_E(Qs, Ks, acc, tx, ty);

    #pragma unroll
    for (int i = 0; i < 8; i++) {
        const int r = ty + 16*i;
        float m = -1e30f;
        #pragma unroll
        for (int j = 0; j < 8; j++) {
            if (isH && (tx + 16*j) == r) continue;
            m = fmaxf(m, acc[i][j]);
        }
        #pragma unroll
        for (int off = 1; off < 16; off <<= 1)
            m = fmaxf(m, __shfl_xor_sync(0xffffffffu, m, off));
        float s = 0.f;
        #pragma unroll
        for (int j = 0; j < 8; j++) {
            if (isH && (tx + 16*j) == r) continue;
            s += __expf(acc[i][j] - m);
        }
        #pragma unroll
        for (int off = 1; off < 16; off <<= 1)
            s += __shfl_xor_sync(0xffffffffu, s, off);
        if (tx == 0) {
            const int p = isH ? (r*WW + f) : (f*WW + r);
            const size_t idx = (size_t)b*NN + p;
            if (isH) { g_mH[idx] = m; g_sH[idx] = s; }
            else     { g_mW[idx] = m; g_sW[idx] = s; }
        }
    }
}

// ---------------- fused out: recompute E -> p -> p@V (tensor cores) ---------
#define PS_STRIDE 136
#define VS_STRIDE 136
#define PS_BYTES  (128*PS_STRIDE*4)    // 69632 (>= Qs+Ks = 66560, overlapped)
#define VS_BYTES  (32*VS_STRIDE*4)     // 17408
#define SMEM_OUT  (PS_BYTES + VS_BYTES + 1024)

__global__ __launch_bounds__(256)
void out_kernel(int isH)
{
    extern __shared__ char sraw[];
    float*    Qs = (float*)sraw;                 // phase 1
    float*    Ks = Qs + 128*QK_STRIDE;
    uint32_t* Ps = (uint32_t*)sraw;              // phase 2 (overlaps Qs/Ks)
    uint32_t* Vs = (uint32_t*)(sraw + PS_BYTES);
    float*    rm = (float*)(sraw + PS_BYTES + VS_BYTES);
    float*    rs = rm + 128;

    const int bz = blockIdx.x;
    const int b = bz >> 7, f = bz & 127;
    const int tid = threadIdx.x;
    const int tx = tid & 15, ty = tid >> 4;
    const int warp = tid >> 5, lane = tid & 31;
    const int g = lane >> 2, tig = lane & 3;
    const int wm = warp >> 2, wn = warp & 3;

    // joint softmax normalizers per row
    if (tid < 128) {
        const int r = tid;
        const size_t idx = (size_t)b*NN + (isH ? (r*WW + f) : (f*WW + r));
        float mh = g_mH[idx], sh = g_sH[idx];
        float mw = g_mW[idx], sw = g_sW[idx];
        float m = fmaxf(mh, mw);
        float s = sh * __expf(mh - m) + sw * __expf(mw - m);
        rm[r] = m; rs[r] = 1.f / s;
    }

    const float* base = g_qk + ((size_t)b*NN + (size_t)(isH ? f : f*WW)) * OQK;
    const size_t rstride = (size_t)(isH ? WW : 1) * OQK;
    load_qk_tiles(base, rstride, Qs, Ks, tid);
    __syncthreads();

    float acc[8][8];
    compute_E(Qs, Ks, acc, tx, ty);
    __syncthreads();   // everyone done reading Qs/Ks before Ps overwrites

    #pragma unroll
    for (int i = 0; i < 8; i++) {
        const int r = ty + 16*i;
        const float m = rm[r], inv = rs[r];
        #pragma unroll
        for (int j = 0; j < 8; j++) {
            const int c = tx + 16*j;
            float v = (isH && c == r) ? 0.f : __expf(acc[i][j] - m) * inv;
            Ps[r*PS_STRIDE + c] = f2tf(v);
        }
    }
    __syncthreads();

    // phase 2: out[row][c] = sum_k p[row][k] * V[k][c]
    const float* vbase = g_v + ((size_t)b*NN + (size_t)(isH ? f : f*WW)) * CC;
    const size_t kstr = (size_t)(isH ? WW : 1) * CC;
    float* outp = isH ? g_oH : g_oW;
    const size_t ob = (size_t)bz * 128 * CC;

    const int vkk = tid >> 3, vc16 = (tid & 7) * 16;

    for (int c0 = 0; c0 < CC; c0 += 128) {
        float acc2[4][4][4];
        #pragma unroll
        for (int i = 0; i < 4; i++)
            #pragma unroll
            for (int j = 0; j < 4; j++)
                #pragma unroll
                for (int r = 0; r < 4; r++) acc2[i][j][r] = 0.f;

        for (int k0 = 0; k0 < 128; k0 += 32) {
            const float* src = vbase + (size_t)(k0 + vkk)*kstr + c0 + vc16;
            uint32_t* dst = Vs + vkk*VS_STRIDE + vc16;
            #pragma unroll
            for (int i = 0; i < 4; i++) {
                float4 v4 = *(const float4*)(src + i*4);
                dst[i*4+0]=f2tf(v4.x); dst[i*4+1]=f2tf(v4.y);
                dst[i*4+2]=f2tf(v4.z); dst[i*4+3]=f2tf(v4.w);
            }
            __syncthreads();
            #pragma unroll
            for (int k8 = 0; k8 < 32; k8 += 8) {
                uint32_t af[4][4], bf[4][2];
                #pragma unroll
                for (int mt = 0; mt < 4; mt++) {
                    const int rb = wm*64 + mt*16;
                    af[mt][0] = Ps[(rb+g  )*PS_STRIDE + k0+k8+tig];
                    af[mt][1] = Ps[(rb+g+8)*PS_STRIDE + k0+k8+tig];
                    af[mt][2] = Ps[(rb+g  )*PS_STRIDE + k0+k8+tig+4];
                    af[mt][3] = Ps[(rb+g+8)*PS_STRIDE + k0+k8+tig+4];
                }
                #pragma unroll
                for (int nt = 0; nt < 4; nt++) {
                    const int cb = wn*32 + nt*8 + g;
                    bf[nt][0] = Vs[(k8+tig  )*VS_STRIDE + cb];
                    bf[nt][1] = Vs[(k8+tig+4)*VS_STRIDE + cb];
                }
                #pragma unroll
                for (int mt = 0; mt < 4; mt++)
                    #pragma unroll
                    for (int nt = 0; nt < 4; nt++)
                        mma_tf32(acc2[mt][nt], af[mt], bf[nt]);
            }
            __syncthreads();
        }

        #pragma unroll
        for (int mt = 0; mt < 4; mt++) {
            const int row = wm*64 + mt*16 + g;
            #pragma unroll
            for (int nt = 0; nt < 4; nt++) {
                const int col = c0 + wn*32 + nt*8 + tig*2;
                *(float2*)(outp + ob + (size_t)row*CC + col) =
                    make_float2(acc2[mt][nt][0], acc2[mt][nt][1]);
                *(float2*)(outp + ob + (size_t)(row+8)*CC + col) =
                    make_float2(acc2[mt][nt][2], acc2[mt][nt][3]);
            }
        }
    }
}

// ---------------- combine: out = gamma*(oH + oW) + x (layout flip) ----------
__global__ void combine_kernel(const float* __restrict__ x,
                               const float* __restrict__ gamma,
                               float* __restrict__ out)
{
    int b = blockIdx.z >> 7;
    int h = blockIdx.z & 127;
    int w0 = blockIdx.x * 32;
    int c0 = blockIdx.y * 32;

    __shared__ float s[32][33];
    int tx = threadIdx.x, ty = threadIdx.y;

    float vW = g_oW[(((size_t)b*HH + h) * WW + (w0 + ty)) * CC + c0 + tx];
    float vH = g_oH[(((size_t)b*WW + (w0 + ty)) * HH + h) * CC + c0 + tx];
    s[ty][tx] = vW + vH;
    __syncthreads();

    size_t oidx = (((size_t)b*CC + c0 + ty) * HH + h) * WW + w0 + tx;
    out[oidx] = gamma[0] * s[tx][ty] + x[oidx];
}

// ---------------- launch -----------------------------------------------------
extern "C" void kernel_launch(void* const* d_in, const int* in_sizes, int n_in,
                              void* d_out, int out_size)
{
    const float* x     = (const float*)d_in[0];
    const float* Wq    = (const float*)d_in[1];
    const float* bq    = (const float*)d_in[2];
    const float* Wk    = (const float*)d_in[3];
    const float* bk    = (const float*)d_in[4];
    const float* Wv    = (const float*)d_in[5];
    const float* bv    = (const float*)d_in[6];
    const float* gamma = (const float*)d_in[7];
    float* out = (float*)d_out;

    cudaFuncSetAttribute(gemm_qkv_tc, cudaFuncAttributeMaxDynamicSharedMemorySize, SMEM_GEMM);
    cudaFuncSetAttribute(stats_kernel, cudaFuncAttributeMaxDynamicSharedMemorySize, SMEM_STATS);
    cudaFuncSetAttribute(out_kernel,   cudaFuncAttributeMaxDynamicSharedMemorySize, SMEM_OUT);

    // 0) pack q/k weights
    pack_wqk<<<128, 256>>>(Wq, bq, Wk, bk);

    // 1) qk = [Wq;Wk] @ x  -> g_qk[b][n][128]
    gemm_qkv_tc<<<dim3(1, NN/128, BB), 256, SMEM_GEMM>>>(x, nullptr, nullptr, 0);
    // 2) v = Wv @ x        -> g_v[b][n][512]
    gemm_qkv_tc<<<dim3(CC/128, NN/128, BB), 256, SMEM_GEMM>>>(x, Wv, bv, 1);

    // 3) softmax stats (m, s) per pixel, per branch
    stats_kernel<<<BB*WW, 256, SMEM_STATS>>>(1);   // H branch (per b,w)
    stats_kernel<<<BB*HH, 256, SMEM_STATS>>>(0);   // W branch (per b,h)

    // 4) fused energy-recompute + softmax + p@V
    out_kernel<<<BB*WW, 256, SMEM_OUT>>>(1);       // oH
    out_kernel<<<BB*HH, 256, SMEM_OUT>>>(0);       // oW

    // 5) combine + residual
    combine_kernel<<<dim3(WW/32, CC/32, BB*HH), dim3(32, 32)>>>(x, gamma, out);
}

// round 4
// speedup vs baseline: 1.0903x; 1.0903x over previous
#include <cuda_runtime.h>
#include <math.h>
#include <stdint.h>

// Problem constants
#define BB 4
#define CC 512
#define HH 128
#define WW 128
#define NN (HH*WW)          // 16384
#define CQ 64
#define OQK 128             // fused q(64) + k(64)

// ---------------- scratch (device globals; no allocation allowed) -----------
__device__ float g_qk[(size_t)BB*NN*OQK];       //  qk_t[b][n][0..63]=q, [64..127]=k
__device__ float g_v [(size_t)BB*NN*CC];        //  v_t[b][n][c]
__device__ float g_oH[(size_t)BB*NN*CC];        //  oH[((b*W+w)*H+h)*C + c]
__device__ float g_oW[(size_t)BB*NN*CC];        //  oW[((b*H+h)*W+w)*C + c]
__device__ float g_mH[(size_t)BB*NN];
__device__ float g_sH[(size_t)BB*NN];
__device__ float g_mW[(size_t)BB*NN];
__device__ float g_sW[(size_t)BB*NN];
__device__ float g_Wqk[OQK*CC];
__device__ float g_bqk[OQK];

// ---------------- tf32 mma helpers ------------------------------------------
__device__ __forceinline__ uint32_t f2tf(float f) {
    uint32_t u;
    asm("cvt.rna.tf32.f32 %0, %1;" : "=r"(u) : "f"(f));
    return u;
}

__device__ __forceinline__ void mma_tf32(float c[4], const uint32_t a[4], const uint32_t b[2]) {
    asm volatile(
        "mma.sync.aligned.m16n8k8.row.col.f32.tf32.tf32.f32 "
        "{%0,%1,%2,%3}, {%4,%5,%6,%7}, {%8,%9}, {%0,%1,%2,%3};"
        : "+f"(c[0]), "+f"(c[1]), "+f"(c[2]), "+f"(c[3])
        : "r"(a[0]), "r"(a[1]), "r"(a[2]), "r"(a[3]), "r"(b[0]), "r"(b[1]));
}

__device__ __forceinline__ void split_store(float v, uint32_t* hi, uint32_t* lo) {
    uint32_t h = f2tf(v);
    *hi = h;
    *lo = f2tf(v - __uint_as_float(h));
}

// ---------------- pack Wq,Wk -> combined ------------------------------------
__global__ void pack_wqk(const float* __restrict__ Wq, const float* __restrict__ bq,
                         const float* __restrict__ Wk, const float* __restrict__ bk)
{
    int i = blockIdx.x * blockDim.x + threadIdx.x;
    if (i < CQ*CC) {
        g_Wqk[i]          = Wq[i];
        g_Wqk[CQ*CC + i]  = Wk[i];
    }
    if (i < CQ) { g_bqk[i] = bq[i]; g_bqk[CQ + i] = bk[i]; }
}

// ---------------- TC GEMM (double-buffered): out_t[b][n][o] -----------------
#define AS_STRIDE 136
#define BS_STRIDE 36
#define SMEM_GEMM ((2*32*AS_STRIDE + 2*128*BS_STRIDE) * 4)

__global__ __launch_bounds__(256)
void gemm_qkv_tc(const float* __restrict__ X, const float* __restrict__ Wp,
                 const float* __restrict__ bp, int mode)
{
    extern __shared__ uint32_t smem_u[];
    uint32_t* As = smem_u;                    // [2][32][136]  (k, m)
    uint32_t* Bs = smem_u + 2*32*AS_STRIDE;   // [2][128][36]  (o, k)

    const int O = mode ? CC : OQK;
    const float* Wm   = mode ? Wp : g_Wqk;
    const float* bias = mode ? bp : g_bqk;
    float* outp       = mode ? g_v : g_qk;

    const int b  = blockIdx.z;
    const int n0 = blockIdx.y * 128;
    const int o0 = blockIdx.x * 128;

    const int tid  = threadIdx.x;
    const int warp = tid >> 5, lane = tid & 31;
    const int g = lane >> 2, tig = lane & 3;
    const int wm = warp >> 2, wn = warp & 3;

    const float* Xp = X + (size_t)b*CC*NN + n0;
    const float* Wb = Wm + (size_t)o0*CC;

    const int col4 = tid & 31, krowA = tid >> 5;
    const int orow = tid >> 1, kcB = (tid & 1) * 16;

    float4 ar[4], br[4];
    #pragma unroll
    for (int it = 0; it < 4; it++) {
        ar[it] = *(const float4*)(Xp + (size_t)(krowA + it*8)*NN + col4*4);
        br[it] = *(const float4*)(Wb + (size_t)orow*CC + kcB + it*4);
    }
    {
        #pragma unroll
        for (int it = 0; it < 4; it++) {
            uint32_t* d = As + (krowA + it*8)*AS_STRIDE + col4*4;
            d[0]=f2tf(ar[it].x); d[1]=f2tf(ar[it].y); d[2]=f2tf(ar[it].z); d[3]=f2tf(ar[it].w);
            uint32_t* e = Bs + orow*BS_STRIDE + kcB + it*4;
            e[0]=f2tf(br[it].x); e[1]=f2tf(br[it].y); e[2]=f2tf(br[it].z); e[3]=f2tf(br[it].w);
        }
    }
    __syncthreads();

    float acc[4][4][4];
    #pragma unroll
    for (int i = 0; i < 4; i++)
        #pragma unroll
        for (int j = 0; j < 4; j++)
            #pragma unroll
            for (int r = 0; r < 4; r++) acc[i][j][r] = 0.f;

    for (int t = 0; t < 16; t++) {
        const int cur = t & 1;
        if (t < 15) {
            const int c1 = (t+1)*32;
            #pragma unroll
            for (int it = 0; it < 4; it++) {
                ar[it] = *(const float4*)(Xp + (size_t)(c1 + krowA + it*8)*NN + col4*4);
                br[it] = *(const float4*)(Wb + (size_t)orow*CC + c1 + kcB + it*4);
            }
        }
        const uint32_t* Ac = As + cur*32*AS_STRIDE;
        const uint32_t* Bc = Bs + cur*128*BS_STRIDE;
        #pragma unroll
        for (int k8 = 0; k8 < 32; k8 += 8) {
            uint32_t af[4][4], bf[4][2];
            #pragma unroll
            for (int mt = 0; mt < 4; mt++) {
                const int rb = wm*64 + mt*16;
                af[mt][0] = Ac[(k8+tig  )*AS_STRIDE + rb + g];
                af[mt][1] = Ac[(k8+tig  )*AS_STRIDE + rb + g + 8];
                af[mt][2] = Ac[(k8+tig+4)*AS_STRIDE + rb + g];
                af[mt][3] = Ac[(k8+tig+4)*AS_STRIDE + rb + g + 8];
            }
            #pragma unroll
            for (int nt = 0; nt < 4; nt++) {
                const int cb = wn*32 + nt*8 + g;
                bf[nt][0] = Bc[cb*BS_STRIDE + k8 + tig];
                bf[nt][1] = Bc[cb*BS_STRIDE + k8 + tig + 4];
            }
            #pragma unroll
            for (int mt = 0; mt < 4; mt++)
                #pragma unroll
                for (int nt = 0; nt < 4; nt++)
                    mma_tf32(acc[mt][nt], af[mt], bf[nt]);
        }
        if (t < 15) {
            uint32_t* Ab = As + (cur^1)*32*AS_STRIDE;
            uint32_t* Bb = Bs + (cur^1)*128*BS_STRIDE;
            #pragma unroll
            for (int it = 0; it < 4; it++) {
                uint32_t* d = Ab + (krowA + it*8)*AS_STRIDE + col4*4;
                d[0]=f2tf(ar[it].x); d[1]=f2tf(ar[it].y); d[2]=f2tf(ar[it].z); d[3]=f2tf(ar[it].w);
                uint32_t* e = Bb + orow*BS_STRIDE + kcB + it*4;
                e[0]=f2tf(br[it].x); e[1]=f2tf(br[it].y); e[2]=f2tf(br[it].z); e[3]=f2tf(br[it].w);
            }
        }
        __syncthreads();
    }

    #pragma unroll
    for (int mt = 0; mt < 4; mt++) {
        int row = n0 + wm*64 + mt*16 + g;
        #pragma unroll
        for (int nt = 0; nt < 4; nt++) {
            int col = o0 + wn*32 + nt*8 + tig*2;
            float b0 = bias[col], b1 = bias[col + 1];
            size_t base0 = ((size_t)b * NN + row) * O + col;
            size_t base1 = base0 + (size_t)8 * O;
            *(float2*)(outp + base0) = make_float2(acc[mt][nt][0] + b0, acc[mt][nt][1] + b1);
            *(float2*)(outp + base1) = make_float2(acc[mt][nt][2] + b0, acc[mt][nt][3] + b1);
        }
    }
}

// ---------------- shared: load q/k rows, split to tf32 hi/lo in smem --------
#define QKS 68                    // stride: (4g+tig)%32 distinct -> conflict-free
#define QK_WORDS (128*QKS)        // 8704 words per array

__device__ __forceinline__ void load_qk_split(const float* __restrict__ base, size_t rstride,
                                              uint32_t* Qhi, uint32_t* Qlo,
                                              uint32_t* Khi, uint32_t* Klo, int tid)
{
    const int row = tid >> 1, half = tid & 1;
    const float* src = base + (size_t)row * rstride + half*32;
    const int off = row*QKS + half*32;
    #pragma unroll
    for (int i = 0; i < 8; i++) {
        float4 q4 = *(const float4*)(src + i*4);
        float4 k4 = *(const float4*)(src + 64 + i*4);
        split_store(q4.x, &Qhi[off+i*4+0], &Qlo[off+i*4+0]);
        split_store(q4.y, &Qhi[off+i*4+1], &Qlo[off+i*4+1]);
        split_store(q4.z, &Qhi[off+i*4+2], &Qlo[off+i*4+2]);
        split_store(q4.w, &Qhi[off+i*4+3], &Qlo[off+i*4+3]);
        split_store(k4.x, &Khi[off+i*4+0], &Klo[off+i*4+0]);
        split_store(k4.y, &Khi[off+i*4+1], &Klo[off+i*4+1]);
        split_store(k4.z, &Khi[off+i*4+2], &Klo[off+i*4+2]);
        split_store(k4.w, &Khi[off+i*4+3], &Klo[off+i*4+3]);
    }
}

// E = Q·K^T via 3-term tf32 split mma (fp32-accurate). Warp tile 64x32.
__device__ __forceinline__ void compute_E_tc(const uint32_t* Qhi, const uint32_t* Qlo,
                                             const uint32_t* Khi, const uint32_t* Klo,
                                             float acc[4][4][4],
                                             int wm, int wn, int g, int tig)
{
    #pragma unroll
    for (int i = 0; i < 4; i++)
        #pragma unroll
        for (int j = 0; j < 4; j++)
            #pragma unroll
            for (int r = 0; r < 4; r++) acc[i][j][r] = 0.f;

    #pragma unroll
    for (int k8 = 0; k8 < 64; k8 += 8) {
        uint32_t ah[4][4], al[4][4], bh[4][2], bl[4][2];
        #pragma unroll
        for (int mt = 0; mt < 4; mt++) {
            const int rb = wm*64 + mt*16;
            ah[mt][0] = Qhi[(rb+g  )*QKS + k8+tig];
            ah[mt][1] = Qhi[(rb+g+8)*QKS + k8+tig];
            ah[mt][2] = Qhi[(rb+g  )*QKS + k8+tig+4];
            ah[mt][3] = Qhi[(rb+g+8)*QKS + k8+tig+4];
            al[mt][0] = Qlo[(rb+g  )*QKS + k8+tig];
            al[mt][1] = Qlo[(rb+g+8)*QKS + k8+tig];
            al[mt][2] = Qlo[(rb+g  )*QKS + k8+tig+4];
            al[mt][3] = Qlo[(rb+g+8)*QKS + k8+tig+4];
        }
        #pragma unroll
        for (int nt = 0; nt < 4; nt++) {
            const int cb = wn*32 + nt*8 + g;
            bh[nt][0] = Khi[cb*QKS + k8+tig];
            bh[nt][1] = Khi[cb*QKS + k8+tig+4];
            bl[nt][0] = Klo[cb*QKS + k8+tig];
            bl[nt][1] = Klo[cb*QKS + k8+tig+4];
        }
        #pragma unroll
        for (int mt = 0; mt < 4; mt++)
            #pragma unroll
            for (int nt = 0; nt < 4; nt++) {
                mma_tf32(acc[mt][nt], ah[mt], bh[nt]);
                mma_tf32(acc[mt][nt], ah[mt], bl[nt]);
                mma_tf32(acc[mt][nt], al[mt], bh[nt]);
            }
    }
}

// ---------------- stats: per-row (m, s) of eH / eW (TC energy) --------------
#define SMEM_STATS ((4*QK_WORDS + 512 + 512 + 128) * 4)

__global__ __launch_bounds__(256)
void stats_kernel()
{
    extern __shared__ uint32_t sm[];
    uint32_t* Qhi = sm;
    uint32_t* Qlo = sm + QK_WORDS;
    uint32_t* Khi = sm + 2*QK_WORDS;
    uint32_t* Klo = sm + 3*QK_WORDS;
    float* pm  = (float*)(sm + 4*QK_WORDS);   // [128][4]
    float* ps2 = pm + 512;                    // [128][4]
    float* rm  = ps2 + 512;                   // [128]

    const int isH = (blockIdx.y == 0);
    const int bz = blockIdx.x;
    const int b = bz >> 7, f = bz & 127;
    const int tid = threadIdx.x;
    const int warp = tid >> 5, lane = tid & 31;
    const int g = lane >> 2, tig = lane & 3;
    const int wm = warp >> 2, wn = warp & 3;

    const float* base = g_qk + ((size_t)b*NN + (size_t)(isH ? f : f*WW)) * OQK;
    const size_t rstride = (size_t)(isH ? WW : 1) * OQK;
    load_qk_split(base, rstride, Qhi, Qlo, Khi, Klo, tid);
    __syncthreads();

    float acc[4][4][4];
    compute_E_tc(Qhi, Qlo, Khi, Klo, acc, wm, wn, g, tig);

    // per-warp row max over this warp's 32 cols
    #pragma unroll
    for (int mt = 0; mt < 4; mt++) {
        const int r0 = wm*64 + mt*16 + g, r1 = r0 + 8;
        float m0 = -1e30f, m1 = -1e30f;
        #pragma unroll
        for (int nt = 0; nt < 4; nt++)
            #pragma unroll
            for (int cc = 0; cc < 2; cc++) {
                const int c = wn*32 + nt*8 + tig*2 + cc;
                if (!(isH && c == r0)) m0 = fmaxf(m0, acc[mt][nt][cc]);
                if (!(isH && c == r1)) m1 = fmaxf(m1, acc[mt][nt][2+cc]);
            }
        m0 = fmaxf(m0, __shfl_xor_sync(0xffffffffu, m0, 1));
        m0 = fmaxf(m0, __shfl_xor_sync(0xffffffffu, m0, 2));
        m1 = fmaxf(m1, __shfl_xor_sync(0xffffffffu, m1, 1));
        m1 = fmaxf(m1, __shfl_xor_sync(0xffffffffu, m1, 2));
        if (tig == 0) { pm[r0*4 + wn] = m0; pm[r1*4 + wn] = m1; }
    }
    __syncthreads();

    if (tid < 128) {
        float m = fmaxf(fmaxf(pm[tid*4], pm[tid*4+1]), fmaxf(pm[tid*4+2], pm[tid*4+3]));
        rm[tid] = m;
    }
    __syncthreads();

    #pragma unroll
    for (int mt = 0; mt < 4; mt++) {
        const int r0 = wm*64 + mt*16 + g, r1 = r0 + 8;
        const float m0 = rm[r0], m1 = rm[r1];
        float s0 = 0.f, s1 = 0.f;
        #pragma unroll
        for (int nt = 0; nt < 4; nt++)
            #pragma unroll
            for (int cc = 0; cc < 2; cc++) {
                const int c = wn*32 + nt*8 + tig*2 + cc;
                if (!(isH && c == r0)) s0 += __expf(acc[mt][nt][cc]   - m0);
                if (!(isH && c == r1)) s1 += __expf(acc[mt][nt][2+cc] - m1);
            }
        s0 += __shfl_xor_sync(0xffffffffu, s0, 1);
        s0 += __shfl_xor_sync(0xffffffffu, s0, 2);
        s1 += __shfl_xor_sync(0xffffffffu, s1, 1);
        s1 += __shfl_xor_sync(0xffffffffu, s1, 2);
        if (tig == 0) { ps2[r0*4 + wn] = s0; ps2[r1*4 + wn] = s1; }
    }
    __syncthreads();

    if (tid < 128) {
        const int r = tid;
        float s = ps2[r*4] + ps2[r*4+1] + ps2[r*4+2] + ps2[r*4+3];
        const int p = isH ? (r*WW + f) : (f*WW + r);
        const size_t idx = (size_t)b*NN + p;
        if (isH) { g_mH[idx] = rm[r]; g_sH[idx] = s; }
        else     { g_mW[idx] = rm[r]; g_sW[idx] = s; }
    }
}

// ---------------- fused out: TC-E -> p -> p@V (double-buffered V) -----------
#define PS_STRIDE 132             // (4g+tig)%32 distinct -> conflict-free A-frags
#define VS_STRIDE 136
#define VS_WORDS  (32*VS_STRIDE)  // 4352
#define SMEM_OUT  ((4*QK_WORDS + 2*VS_WORDS + 256) * 4)

__global__ __launch_bounds__(256)
void out_kernel()
{
    extern __shared__ uint32_t sm[];
    uint32_t* Qhi = sm;
    uint32_t* Qlo = sm + QK_WORDS;
    uint32_t* Khi = sm + 2*QK_WORDS;
    uint32_t* Klo = sm + 3*QK_WORDS;
    uint32_t* Ps  = sm;                         // overlaps Qhi+Qlo after E
    uint32_t* Vs  = sm + 4*QK_WORDS;            // [2][32][136]
    float* rm = (float*)(sm + 4*QK_WORDS + 2*VS_WORDS);
    float* rs = rm + 128;

    const int isH = (blockIdx.y == 0);
    const int bz = blockIdx.x;
    const int b = bz >> 7, f = bz & 127;
    const int tid = threadIdx.x;
    const int warp = tid >> 5, lane = tid & 31;
    const int g = lane >> 2, tig = lane & 3;
    const int wm = warp >> 2, wn = warp & 3;

    // joint softmax normalizers per row
    if (tid < 128) {
        const int r = tid;
        const size_t idx = (size_t)b*NN + (isH ? (r*WW + f) : (f*WW + r));
        float mh = g_mH[idx], sh = g_sH[idx];
        float mw = g_mW[idx], sw = g_sW[idx];
        float m = fmaxf(mh, mw);
        float s = sh * __expf(mh - m) + sw * __expf(mw - m);
        rm[r] = m; rs[r] = 1.f / s;
    }

    const float* base = g_qk + ((size_t)b*NN + (size_t)(isH ? f : f*WW)) * OQK;
    const size_t rstride = (size_t)(isH ? WW : 1) * OQK;
    load_qk_split(base, rstride, Qhi, Qlo, Khi, Klo, tid);
    __syncthreads();

    float acc[4][4][4];
    compute_E_tc(Qhi, Qlo, Khi, Klo, acc, wm, wn, g, tig);
    __syncthreads();   // done reading Qhi/Qlo; rm/rs visible

    // p = exp(e - m) * inv, write tf32 into Ps
    #pragma unroll
    for (int mt = 0; mt < 4; mt++) {
        const int r0 = wm*64 + mt*16 + g, r1 = r0 + 8;
        const float m0 = rm[r0], i0 = rs[r0];
        const float m1 = rm[r1], i1 = rs[r1];
        #pragma unroll
        for (int nt = 0; nt < 4; nt++)
            #pragma unroll
            for (int cc = 0; cc < 2; cc++) {
                const int c = wn*32 + nt*8 + tig*2 + cc;
                float p0 = (isH && c == r0) ? 0.f : __expf(acc[mt][nt][cc]   - m0) * i0;
                float p1 = (isH && c == r1) ? 0.f : __expf(acc[mt][nt][2+cc] - m1) * i1;
                Ps[r0*PS_STRIDE + c] = f2tf(p0);
                Ps[r1*PS_STRIDE + c] = f2tf(p1);
            }
    }
    __syncthreads();

    // p@V: out[row][c] = sum_k p[row][k] * V[k][c], 16 tiles (4 c0 x 4 k0)
    const float* vbase = g_v + ((size_t)b*NN + (size_t)(isH ? f : f*WW)) * CC;
    const size_t kstr = (size_t)(isH ? WW : 1) * CC;
    float* outp = isH ? g_oH : g_oW;
    const size_t ob = (size_t)bz * 128 * CC;

    const int vkk = tid >> 3, vc16 = (tid & 7) * 16;

    float4 vr[4];
    #pragma unroll
    for (int i = 0; i < 4; i++)
        vr[i] = *(const float4*)(vbase + (size_t)vkk*kstr + vc16 + i*4);

    float acc2[4][4][4];

    for (int t = 0; t < 16; t++) {
        const int c0 = (t >> 2) * 128;
        const int k0 = (t & 3) * 32;
        const int cur = t & 1;

        uint32_t* dst = Vs + cur*VS_WORDS + vkk*VS_STRIDE + vc16;
        #pragma unroll
        for (int i = 0; i < 4; i++) {
            dst[i*4+0]=f2tf(vr[i].x); dst[i*4+1]=f2tf(vr[i].y);
            dst[i*4+2]=f2tf(vr[i].z); dst[i*4+3]=f2tf(vr[i].w);
        }
        __syncthreads();

        if (t < 15) {
            const int tn = t + 1;
            const int c0n = (tn >> 2) * 128, k0n = (tn & 3) * 32;
            const float* src = vbase + (size_t)(k0n + vkk)*kstr + c0n + vc16;
            #pragma unroll
            for (int i = 0; i < 4; i++) vr[i] = *(const float4*)(src + i*4);
        }

        if (k0 == 0) {
            #pragma unroll
            for (int i = 0; i < 4; i++)
                #pragma unroll
                for (int j = 0; j < 4; j++)
                    #pragma unroll
                    for (int r = 0; r < 4; r++) acc2[i][j][r] = 0.f;
        }

        const uint32_t* Vc = Vs + cur*VS_WORDS;
        #pragma unroll
        for (int k8 = 0; k8 < 32; k8 += 8) {
            uint32_t af[4][4], bf[4][2];
            #pragma unroll
            for (int mt = 0; mt < 4; mt++) {
                const int rb = wm*64 + mt*16;
                af[mt][0] = Ps[(rb+g  )*PS_STRIDE + k0+k8+tig];
                af[mt][1] = Ps[(rb+g+8)*PS_STRIDE + k0+k8+tig];
                af[mt][2] = Ps[(rb+g  )*PS_STRIDE + k0+k8+tig+4];
                af[mt][3] = Ps[(rb+g+8)*PS_STRIDE + k0+k8+tig+4];
            }
            #pragma unroll
            for (int nt = 0; nt < 4; nt++) {
                const int cb = wn*32 + nt*8 + g;
                bf[nt][0] = Vc[(k8+tig  )*VS_STRIDE + cb];
                bf[nt][1] = Vc[(k8+tig+4)*VS_STRIDE + cb];
            }
            #pragma unroll
            for (int mt = 0; mt < 4; mt++)
                #pragma unroll
                for (int nt = 0; nt < 4; nt++)
                    mma_tf32(acc2[mt][nt], af[mt], bf[nt]);
        }

        if (k0 == 96) {
            #pragma unroll
            for (int mt = 0; mt < 4; mt++) {
                const int row = wm*64 + mt*16 + g;
                #pragma unroll
                for (int nt = 0; nt < 4; nt++) {
                    const int col = c0 + wn*32 + nt*8 + tig*2;
                    *(float2*)(outp + ob + (size_t)row*CC + col) =
                        make_float2(acc2[mt][nt][0], acc2[mt][nt][1]);
                    *(float2*)(outp + ob + (size_t)(row+8)*CC + col) =
                        make_float2(acc2[mt][nt][2], acc2[mt][nt][3]);
                }
            }
        }
        __syncthreads();
    }
}

// ---------------- combine: out = gamma*(oH + oW) + x (layout flip) ----------
__global__ void combine_kernel(const float* __restrict__ x,
                               const float* __restrict__ gamma,
                               float* __restrict__ out)
{
    int b = blockIdx.z >> 7;
    int h = blockIdx.z & 127;
    int w0 = blockIdx.x * 32;
    int c0 = blockIdx.y * 32;

    __shared__ float s[32][33];
    int tx = threadIdx.x, ty = threadIdx.y;

    float vW = g_oW[(((size_t)b*HH + h) * WW + (w0 + ty)) * CC + c0 + tx];
    float vH = g_oH[(((size_t)b*WW + (w0 + ty)) * HH + h) * CC + c0 + tx];
    s[ty][tx] = vW + vH;
    __syncthreads();

    size_t oidx = (((size_t)b*CC + c0 + ty) * HH + h) * WW + w0 + tx;
    out[oidx] = gamma[0] * s[tx][ty] + x[oidx];
}

// ---------------- launch -----------------------------------------------------
extern "C" void kernel_launch(void* const* d_in, const int* in_sizes, int n_in,
                              void* d_out, int out_size)
{
    const float* x     = (const float*)d_in[0];
    const float* Wq    = (const float*)d_in[1];
    const float* bq    = (const float*)d_in[2];
    const float* Wk    = (const float*)d_in[3];
    const float* bk    = (const float*)d_in[4];
    const float* Wv    = (const float*)d_in[5];
    const float* bv    = (const float*)d_in[6];
    const float* gamma = (const float*)d_in[7];
    float* out = (float*)d_out;

    cudaFuncSetAttribute(gemm_qkv_tc,  cudaFuncAttributeMaxDynamicSharedMemorySize, SMEM_GEMM);
    cudaFuncSetAttribute(stats_kernel, cudaFuncAttributeMaxDynamicSharedMemorySize, SMEM_STATS);
    cudaFuncSetAttribute(out_kernel,   cudaFuncAttributeMaxDynamicSharedMemorySize, SMEM_OUT);

    // 0) pack q/k weights
    pack_wqk<<<128, 256>>>(Wq, bq, Wk, bk);

    // 1) qk = [Wq;Wk] @ x  -> g_qk[b][n][128]
    gemm_qkv_tc<<<dim3(1, NN/128, BB), 256, SMEM_GEMM>>>(x, nullptr, nullptr, 0);
    // 2) v = Wv @ x        -> g_v[b][n][512]
    gemm_qkv_tc<<<dim3(CC/128, NN/128, BB), 256, SMEM_GEMM>>>(x, Wv, bv, 1);

    // 3) softmax stats (m, s) per pixel, both branches in one launch
    stats_kernel<<<dim3(BB*128, 2), 256, SMEM_STATS>>>();

    // 4) fused TC energy-recompute + softmax + p@V, both branches
    out_kernel<<<dim3(BB*128, 2), 256, SMEM_OUT>>>();

    // 5) combine + residual
    combine_kernel<<<dim3(WW/32, CC/32, BB*HH), dim3(32, 32)>>>(x, gamma, out);
}

// round 5
// speedup vs baseline: 1.2166x; 1.1158x over previous
#include <cuda_runtime.h>
#include <math.h>
#include <stdint.h>

// Problem constants
#define BB 4
#define CC 512
#define HH 128
#define WW 128
#define NN (HH*WW)          // 16384
#define CQ 64
#define OQK 128             // fused q(64) + k(64)

// ---------------- scratch (device globals; no allocation allowed) -----------
__device__ float g_qk[(size_t)BB*NN*OQK];       //  qk_t[b][n][0..63]=q, [64..127]=k
__device__ float g_v [(size_t)BB*NN*CC];        //  v_t[b][n][c]
__device__ float g_eH[(size_t)BB*HH*WW*HH];     //  eH[b][h][w][i]
__device__ float g_eW[(size_t)BB*HH*WW*WW];     //  eW[b][h][w][j]
__device__ float g_oH[(size_t)BB*NN*CC];        //  oH[((b*W+w)*H+h)*C + c]
__device__ float g_Wqk[OQK*CC];
__device__ float g_bqk[OQK];

// ---------------- tf32 mma helpers ------------------------------------------
__device__ __forceinline__ uint32_t f2tf(float f) {
    uint32_t u;
    asm("cvt.rna.tf32.f32 %0, %1;" : "=r"(u) : "f"(f));
    return u;
}

__device__ __forceinline__ void mma_tf32(float c[4], const uint32_t a[4], const uint32_t b[2]) {
    asm volatile(
        "mma.sync.aligned.m16n8k8.row.col.f32.tf32.tf32.f32 "
        "{%0,%1,%2,%3}, {%4,%5,%6,%7}, {%8,%9}, {%0,%1,%2,%3};"
        : "+f"(c[0]), "+f"(c[1]), "+f"(c[2]), "+f"(c[3])
        : "r"(a[0]), "r"(a[1]), "r"(a[2]), "r"(a[3]), "r"(b[0]), "r"(b[1]));
}

// ---------------- pack Wq,Wk -> combined ------------------------------------
__global__ void pack_wqk(const float* __restrict__ Wq, const float* __restrict__ bq,
                         const float* __restrict__ Wk, const float* __restrict__ bk)
{
    int i = blockIdx.x * blockDim.x + threadIdx.x;
    if (i < CQ*CC) {
        g_Wqk[i]          = Wq[i];
        g_Wqk[CQ*CC + i]  = Wk[i];
    }
    if (i < CQ) { g_bqk[i] = bq[i]; g_bqk[CQ + i] = bk[i]; }
}

// ---------------- TC GEMM (double-buffered): out_t[b][n][o] -----------------
#define AS_STRIDE 136
#define BS_STRIDE 36
#define SMEM_GEMM ((2*32*AS_STRIDE + 2*128*BS_STRIDE) * 4)

__global__ __launch_bounds__(256)
void gemm_qkv_tc(const float* __restrict__ X, const float* __restrict__ Wp,
                 const float* __restrict__ bp, int mode)
{
    extern __shared__ uint32_t smem_u[];
    uint32_t* As = smem_u;                    // [2][32][136]  (k, m)
    uint32_t* Bs = smem_u + 2*32*AS_STRIDE;   // [2][128][36]  (o, k)

    const int O = mode ? CC : OQK;
    const float* Wm   = mode ? Wp : g_Wqk;
    const float* bias = mode ? bp : g_bqk;
    float* outp       = mode ? g_v : g_qk;

    const int b  = blockIdx.z;
    const int n0 = blockIdx.y * 128;
    const int o0 = blockIdx.x * 128;

    const int tid  = threadIdx.x;
    const int warp = tid >> 5, lane = tid & 31;
    const int g = lane >> 2, tig = lane & 3;
    const int wm = warp >> 2, wn = warp & 3;

    const float* Xp = X + (size_t)b*CC*NN + n0;
    const float* Wb = Wm + (size_t)o0*CC;

    const int col4 = tid & 31, krowA = tid >> 5;
    const int orow = tid >> 1, kcB = (tid & 1) * 16;

    float4 ar[4], br[4];
    #pragma unroll
    for (int it = 0; it < 4; it++) {
        ar[it] = *(const float4*)(Xp + (size_t)(krowA + it*8)*NN + col4*4);
        br[it] = *(const float4*)(Wb + (size_t)orow*CC + kcB + it*4);
    }
    {
        #pragma unroll
        for (int it = 0; it < 4; it++) {
            uint32_t* d = As + (krowA + it*8)*AS_STRIDE + col4*4;
            d[0]=f2tf(ar[it].x); d[1]=f2tf(ar[it].y); d[2]=f2tf(ar[it].z); d[3]=f2tf(ar[it].w);
            uint32_t* e = Bs + orow*BS_STRIDE + kcB + it*4;
            e[0]=f2tf(br[it].x); e[1]=f2tf(br[it].y); e[2]=f2tf(br[it].z); e[3]=f2tf(br[it].w);
        }
    }
    __syncthreads();

    float acc[4][4][4];
    #pragma unroll
    for (int i = 0; i < 4; i++)
        #pragma unroll
        for (int j = 0; j < 4; j++)
            #pragma unroll
            for (int r = 0; r < 4; r++) acc[i][j][r] = 0.f;

    for (int t = 0; t < 16; t++) {
        const int cur = t & 1;
        if (t < 15) {
            const int c1 = (t+1)*32;
            #pragma unroll
            for (int it = 0; it < 4; it++) {
                ar[it] = *(const float4*)(Xp + (size_t)(c1 + krowA + it*8)*NN + col4*4);
                br[it] = *(const float4*)(Wb + (size_t)orow*CC + c1 + kcB + it*4);
            }
        }
        const uint32_t* Ac = As + cur*32*AS_STRIDE;
        const uint32_t* Bc = Bs + cur*128*BS_STRIDE;
        #pragma unroll
        for (int k8 = 0; k8 < 32; k8 += 8) {
            uint32_t af[4][4], bf[4][2];
            #pragma unroll
            for (int mt = 0; mt < 4; mt++) {
                const int rb = wm*64 + mt*16;
                af[mt][0] = Ac[(k8+tig  )*AS_STRIDE + rb + g];
                af[mt][1] = Ac[(k8+tig  )*AS_STRIDE + rb + g + 8];
                af[mt][2] = Ac[(k8+tig+4)*AS_STRIDE + rb + g];
                af[mt][3] = Ac[(k8+tig+4)*AS_STRIDE + rb + g + 8];
            }
            #pragma unroll
            for (int nt = 0; nt < 4; nt++) {
                const int cb = wn*32 + nt*8 + g;
                bf[nt][0] = Bc[cb*BS_STRIDE + k8 + tig];
                bf[nt][1] = Bc[cb*BS_STRIDE + k8 + tig + 4];
            }
            #pragma unroll
            for (int mt = 0; mt < 4; mt++)
                #pragma unroll
                for (int nt = 0; nt < 4; nt++)
                    mma_tf32(acc[mt][nt], af[mt], bf[nt]);
        }
        if (t < 15) {
            uint32_t* Ab = As + (cur^1)*32*AS_STRIDE;
            uint32_t* Bb = Bs + (cur^1)*128*BS_STRIDE;
            #pragma unroll
            for (int it = 0; it < 4; it++) {
                uint32_t* d = Ab + (krowA + it*8)*AS_STRIDE + col4*4;
                d[0]=f2tf(ar[it].x); d[1]=f2tf(ar[it].y); d[2]=f2tf(ar[it].z); d[3]=f2tf(ar[it].w);
                uint32_t* e = Bb + orow*BS_STRIDE + kcB + it*4;
                e[0]=f2tf(br[it].x); e[1]=f2tf(br[it].y); e[2]=f2tf(br[it].z); e[3]=f2tf(br[it].w);
            }
        }
        __syncthreads();
    }

    #pragma unroll
    for (int mt = 0; mt < 4; mt++) {
        int row = n0 + wm*64 + mt*16 + g;
        #pragma unroll
        for (int nt = 0; nt < 4; nt++) {
            int col = o0 + wn*32 + nt*8 + tig*2;
            float b0 = bias[col], b1 = bias[col + 1];
            size_t base0 = ((size_t)b * NN + row) * O + col;
            size_t base1 = base0 + (size_t)8 * O;
            *(float2*)(outp + base0) = make_float2(acc[mt][nt][0] + b0, acc[mt][nt][1] + b1);
            *(float2*)(outp + base1) = make_float2(acc[mt][nt][2] + b0, acc[mt][nt][3] + b1);
        }
    }
}

// ---------------- energy: E[r][s] = dot64(q_row[r], k_row[s]), vectorized ---
#define EQS 68
__global__ __launch_bounds__(256)
void energy_kernel()
{
    __shared__ float As[64][EQS];
    __shared__ float Bs[64][EQS];

    const int isH  = blockIdx.y >> 2;
    const int quad = blockIdx.y & 3;
    const int b = blockIdx.z, f = blockIdx.x;
    const int r0 = (quad >> 1) * 64;
    const int s0 = (quad & 1) * 64;

    size_t qbase, obase; int rq, ro;
    if (isH) { qbase = ((size_t)b*NN + f) * OQK;            rq = WW*OQK;
               obase = (size_t)b*HH*WW*HH + (size_t)f*HH;   ro = WW*HH; }
    else     { qbase = ((size_t)b*NN + (size_t)f*WW) * OQK; rq = OQK;
               obase = (size_t)b*HH*WW*WW + (size_t)f*WW*WW; ro = WW; }
    float* outp = isH ? g_eH : g_eW;

    const int tid = threadIdx.x;
    const int tx = tid & 15, ty = tid >> 4;

    // vectorized fill: 64 rows x 16 float4 per array
    const int lr = tid >> 4, lc4 = (tid & 15) * 4;
    #pragma unroll
    for (int r = 0; r < 4; r++) {
        const int row = lr + r*16;
        float4 q4 = *(const float4*)(&g_qk[qbase + (size_t)(r0+row)*rq + lc4]);
        float4 k4 = *(const float4*)(&g_qk[qbase + (size_t)(s0+row)*rq + 64 + lc4]);
        *(float4*)&As[row][lc4] = q4;
        *(float4*)&Bs[row][lc4] = k4;
    }
    __syncthreads();

    float acc[4][4];
    #pragma unroll
    for (int i = 0; i < 4; i++)
        #pragma unroll
        for (int j = 0; j < 4; j++) acc[i][j] = 0.f;

    #pragma unroll
    for (int c4 = 0; c4 < 64; c4 += 4) {
        float4 a4[4], b4[4];
        #pragma unroll
        for (int i = 0; i < 4; i++) a4[i] = *(const float4*)&As[ty + 16*i][c4];
        #pragma unroll
        for (int j = 0; j < 4; j++) b4[j] = *(const float4*)&Bs[tx + 16*j][c4];
        #pragma unroll
        for (int i = 0; i < 4; i++)
            #pragma unroll
            for (int j = 0; j < 4; j++) {
                acc[i][j] += a4[i].x * b4[j].x;
                acc[i][j] += a4[i].y * b4[j].y;
                acc[i][j] += a4[i].z * b4[j].z;
                acc[i][j] += a4[i].w * b4[j].w;
            }
    }

    #pragma unroll
    for (int i = 0; i < 4; i++) {
        int r = r0 + ty + 16*i;
        #pragma unroll
        for (int j = 0; j < 4; j++) {
            int s = s0 + tx + 16*j;
            float val = acc[i][j];
            if (isH && r == s) val = -INFINITY;
            outp[obase + (size_t)r * ro + s] = val;
        }
    }
}

// ---------------- softmax over concat(eH[128], eW[128]) per (b,h,w) ---------
__global__ void softmax_kernel()
{
    int gwarp = (blockIdx.x * blockDim.x + threadIdx.x) >> 5;
    int lane  = threadIdx.x & 31;
    if (gwarp >= BB*HH*WW) return;

    float4* pH = (float4*)(g_eH + (size_t)gwarp * HH);
    float4* pW = (float4*)(g_eW + (size_t)gwarp * WW);
    float4 vH = pH[lane];
    float4 vW = pW[lane];

    float m = fmaxf(fmaxf(fmaxf(vH.x, vH.y), fmaxf(vH.z, vH.w)),
                    fmaxf(fmaxf(vW.x, vW.y), fmaxf(vW.z, vW.w)));
    #pragma unroll
    for (int off = 16; off; off >>= 1)
        m = fmaxf(m, __shfl_xor_sync(0xffffffffu, m, off));

    vH.x = __expf(vH.x - m); vH.y = __expf(vH.y - m);
    vH.z = __expf(vH.z - m); vH.w = __expf(vH.w - m);
    vW.x = __expf(vW.x - m); vW.y = __expf(vW.y - m);
    vW.z = __expf(vW.z - m); vW.w = __expf(vW.w - m);

    float s = vH.x + vH.y + vH.z + vH.w + vW.x + vW.y + vW.z + vW.w;
    #pragma unroll
    for (int off = 16; off; off >>= 1)
        s += __shfl_xor_sync(0xffffffffu, s, off);
    float inv = 1.f / s;

    vH.x *= inv; vH.y *= inv; vH.z *= inv; vH.w *= inv;
    vW.x *= inv; vW.y *= inv; vW.z *= inv; vW.w *= inv;
    pH[lane] = vH;
    pW[lane] = vW;
}

// ---------------- shared out-GEMM body macro-free: H branch -----------------
// Out[n][c] = sum_k A[n][k] * V[k][c]; block = (c0 chunk, b*128+f)
#define OAS 36
#define OVS 136

__global__ __launch_bounds__(256)
void out_h_kernel()
{
    __shared__ uint32_t As2[128][OAS];
    __shared__ uint32_t Vs[32][OVS];

    const int bz = blockIdx.y;
    const int b = bz >> 7, f = bz & 127;      // f = w
    const int c0 = blockIdx.x * 128;

    const size_t vbase = ((size_t)b*NN + f) * CC;
    const size_t kstr  = (size_t)WW*CC;
    const size_t abase = (size_t)b*HH*WW*HH + (size_t)f*HH;
    const int anstride = WW*HH;
    const size_t ob = (size_t)bz * 128 * CC;

    const int tid = threadIdx.x;
    const int warp = tid >> 5, lane = tid & 31;
    const int g = lane >> 2, tig = lane & 3;
    const int wm = warp >> 2, wn = warp & 3;

    float acc2[4][4][4];
    #pragma unroll
    for (int i = 0; i < 4; i++)
        #pragma unroll
        for (int j = 0; j < 4; j++)
            #pragma unroll
            for (int r = 0; r < 4; r++) acc2[i][j][r] = 0.f;

    const int nrow = tid >> 1, kcA = (tid & 1) * 16;
    const int krowB = tid >> 3, vc16 = (tid & 7) * 16;

    for (int k0 = 0; k0 < 128; k0 += 32) {
        #pragma unroll
        for (int it = 0; it < 4; it++) {
            float4 v = *(const float4*)(g_eH + abase + (size_t)nrow*anstride + k0 + kcA + it*4);
            uint32_t* d = &As2[nrow][kcA + it*4];
            d[0]=f2tf(v.x); d[1]=f2tf(v.y); d[2]=f2tf(v.z); d[3]=f2tf(v.w);
        }
        {
            const float* src = g_v + vbase + (size_t)(k0 + krowB)*kstr + c0 + vc16;
            uint32_t* d = &Vs[krowB][vc16];
            #pragma unroll
            for (int i = 0; i < 4; i++) {
                float4 v = *(const float4*)(src + i*4);
                d[i*4+0]=f2tf(v.x); d[i*4+1]=f2tf(v.y); d[i*4+2]=f2tf(v.z); d[i*4+3]=f2tf(v.w);
            }
        }
        __syncthreads();
        #pragma unroll
        for (int k8 = 0; k8 < 32; k8 += 8) {
            uint32_t af[4][4], bf[4][2];
            #pragma unroll
            for (int mt = 0; mt < 4; mt++) {
                const int rb = wm*64 + mt*16;
                af[mt][0] = As2[rb+g  ][k8+tig];
                af[mt][1] = As2[rb+g+8][k8+tig];
                af[mt][2] = As2[rb+g  ][k8+tig+4];
                af[mt][3] = As2[rb+g+8][k8+tig+4];
            }
            #pragma unroll
            for (int nt = 0; nt < 4; nt++) {
                const int cb = wn*32 + nt*8 + g;
                bf[nt][0] = Vs[k8+tig  ][cb];
                bf[nt][1] = Vs[k8+tig+4][cb];
            }
            #pragma unroll
            for (int mt = 0; mt < 4; mt++)
                #pragma unroll
                for (int nt = 0; nt < 4; nt++)
                    mma_tf32(acc2[mt][nt], af[mt], bf[nt]);
        }
        __syncthreads();
    }

    #pragma unroll
    for (int mt = 0; mt < 4; mt++) {
        const int row = wm*64 + mt*16 + g;
        #pragma unroll
        for (int nt = 0; nt < 4; nt++) {
            const int col = c0 + wn*32 + nt*8 + tig*2;
            *(float2*)(g_oH + ob + (size_t)row*CC + col) =
                make_float2(acc2[mt][nt][0], acc2[mt][nt][1]);
            *(float2*)(g_oH + ob + (size_t)(row+8)*CC + col) =
                make_float2(acc2[mt][nt][2], acc2[mt][nt][3]);
        }
    }
}

// ---------------- W branch + fused combine (final output) -------------------
__global__ __launch_bounds__(256)
void out_w_kernel(const float* __restrict__ x, const float* __restrict__ gamma,
                  float* __restrict__ out)
{
    __shared__ uint32_t As2[128][OAS];
    __shared__ uint32_t Vs[32][OVS];

    const int bz = blockIdx.y;
    const int b = bz >> 7, f = bz & 127;      // f = h
    const int c0 = blockIdx.x * 128;

    const size_t vbase = ((size_t)b*NN + (size_t)f*WW) * CC;
    const size_t kstr  = CC;
    const size_t abase = (size_t)b*HH*WW*WW + (size_t)f*WW*WW;
    const int anstride = WW;

    const int tid = threadIdx.x;
    const int warp = tid >> 5, lane = tid & 31;
    const int g = lane >> 2, tig = lane & 3;
    const int wm = warp >> 2, wn = warp & 3;

    float acc2[4][4][4];
    #pragma unroll
    for (int i = 0; i < 4; i++)
        #pragma unroll
        for (int j = 0; j < 4; j++)
            #pragma unroll
            for (int r = 0; r < 4; r++) acc2[i][j][r] = 0.f;

    const int nrow = tid >> 1, kcA = (tid & 1) * 16;
    const int krowB = tid >> 3, vc16 = (tid & 7) * 16;

    for (int k0 = 0; k0 < 128; k0 += 32) {
        #pragma unroll
        for (int it = 0; it < 4; it++) {
            float4 v = *(const float4*)(g_eW + abase + (size_t)nrow*anstride + k0 + kcA + it*4);
            uint32_t* d = &As2[nrow][kcA + it*4];
            d[0]=f2tf(v.x); d[1]=f2tf(v.y); d[2]=f2tf(v.z); d[3]=f2tf(v.w);
        }
        {
            const float* src = g_v + vbase + (size_t)(k0 + krowB)*kstr + c0 + vc16;
            uint32_t* d = &Vs[krowB][vc16];
            #pragma unroll
            for (int i = 0; i < 4; i++) {
                float4 v = *(const float4*)(src + i*4);
                d[i*4+0]=f2tf(v.x); d[i*4+1]=f2tf(v.y); d[i*4+2]=f2tf(v.z); d[i*4+3]=f2tf(v.w);
            }
        }
        __syncthreads();
        #pragma unroll
        for (int k8 = 0; k8 < 32; k8 += 8) {
            uint32_t af[4][4], bf[4][2];
            #pragma unroll
            for (int mt = 0; mt < 4; mt++) {
                const int rb = wm*64 + mt*16;
                af[mt][0] = As2[rb+g  ][k8+tig];
                af[mt][1] = As2[rb+g+8][k8+tig];
                af[mt][2] = As2[rb+g  ][k8+tig+4];
                af[mt][3] = As2[rb+g+8][k8+tig+4];
            }
            #pragma unroll
            for (int nt = 0; nt < 4; nt++) {
                const int cb = wn*32 + nt*8 + g;
                bf[nt][0] = Vs[k8+tig  ][cb];
                bf[nt][1] = Vs[k8+tig+4][cb];
            }
            #pragma unroll
            for (int mt = 0; mt < 4; mt++)
                #pragma unroll
                for (int nt = 0; nt < 4; nt++)
                    mma_tf32(acc2[mt][nt], af[mt], bf[nt]);
        }
        __syncthreads();
    }

    // fused epilogue: out[b][c][f][w] = gamma*(accW[w][c] + oH[b][w][f][c]) + x
    // reuse As2 as T[32][136] (transpose strip), Vs as O[128][33] (oH strip)
    float (*T)[136] = reinterpret_cast<float(*)[136]>(&As2[0][0]);
    float (*O)[33]  = reinterpret_cast<float(*)[33]>(&Vs[0][0]);
    const float gm = gamma[0];

    const int orow = tid >> 1, olc = (tid & 1) * 16;  // oH strip load
    const int wlc = tid >> 3, wwo = (tid & 7) * 16;   // out write

    for (int s = 0; s < 4; s++) {
        __syncthreads();
        // load oH strip: O[w][lc] = oH[((b*128 + w)*128 + f)*CC + c0 + s*32 + lc]
        {
            const float* src = g_oH + (((size_t)(b*128 + orow))*128 + f)*CC + c0 + s*32 + olc;
            #pragma unroll
            for (int i = 0; i < 4; i++) {
                float4 v = *(const float4*)(src + i*4);
                O[orow][olc+i*4+0]=v.x; O[orow][olc+i*4+1]=v.y;
                O[orow][olc+i*4+2]=v.z; O[orow][olc+i*4+3]=v.w;
            }
        }
        // warp wn==s owns cols [s*32, s*32+32): transpose its acc into T
        if (wn == s) {
            #pragma unroll
            for (int mt = 0; mt < 4; mt++) {
                const int row = wm*64 + mt*16 + g;
                #pragma unroll
                for (int nt = 0; nt < 4; nt++) {
                    const int lc = nt*8 + tig*2;
                    T[lc  ][row]   = acc2[mt][nt][0];
                    T[lc+1][row]   = acc2[mt][nt][1];
                    T[lc  ][row+8] = acc2[mt][nt][2];
                    T[lc+1][row+8] = acc2[mt][nt][3];
                }
            }
        }
        __syncthreads();
        // write out rows c = c0 + s*32 + wlc, w contiguous
        {
            const int c = c0 + s*32 + wlc;
            const size_t xb = (((size_t)b*CC + c)*HH + f)*WW;
            #pragma unroll
            for (int i = 0; i < 4; i++) {
                const int w = wwo + i*4;
                float4 xv = *(const float4*)(x + xb + w);
                float4 o;
                o.x = gm*(T[wlc][w+0] + O[w+0][wlc]) + xv.x;
                o.y = gm*(T[wlc][w+1] + O[w+1][wlc]) + xv.y;
                o.z = gm*(T[wlc][w+2] + O[w+2][wlc]) + xv.z;
                o.w = gm*(T[wlc][w+3] + O[w+3][wlc]) + xv.w;
                *(float4*)(out + xb + w) = o;
            }
        }
    }
}

// ---------------- launch -----------------------------------------------------
extern "C" void kernel_launch(void* const* d_in, const int* in_sizes, int n_in,
                              void* d_out, int out_size)
{
    const float* x     = (const float*)d_in[0];
    const float* Wq    = (const float*)d_in[1];
    const float* bq    = (const float*)d_in[2];
    const float* Wk    = (const float*)d_in[3];
    const float* bk    = (const float*)d_in[4];
    const float* Wv    = (const float*)d_in[5];
    const float* bv    = (const float*)d_in[6];
    const float* gamma = (const float*)d_in[7];
    float* out = (float*)d_out;

    cudaFuncSetAttribute(gemm_qkv_tc, cudaFuncAttributeMaxDynamicSharedMemorySize, SMEM_GEMM);

    // 0) pack q/k weights
    pack_wqk<<<128, 256>>>(Wq, bq, Wk, bk);

    // 1) qk = [Wq;Wk] @ x  -> g_qk[b][n][128]
    gemm_qkv_tc<<<dim3(1, NN/128, BB), 256, SMEM_GEMM>>>(x, nullptr, nullptr, 0);
    // 2) v = Wv @ x        -> g_v[b][n][512]
    gemm_qkv_tc<<<dim3(CC/128, NN/128, BB), 256, SMEM_GEMM>>>(x, Wv, bv, 1);

    // 3) energies, both branches
    energy_kernel<<<dim3(128, 8, BB), 256>>>();

    // 4) joint softmax
    softmax_kernel<<<(BB*HH*WW*32 + 255) / 256, 256>>>();

    // 5) H-branch p@V -> g_oH
    out_h_kernel<<<dim3(CC/128, BB*128), 256>>>();
    // 6) W-branch p@V + fused combine -> out
    out_w_kernel<<<dim3(CC/128, BB*128), 256>>>(x, gamma, out);
}

// round 6
// speedup vs baseline: 1.2206x; 1.0033x over previous
#include <cuda_runtime.h>
#include <math.h>
#include <stdint.h>

// Problem constants
#define BB 4
#define CC 512
#define HH 128
#define WW 128
#define NN (HH*WW)          // 16384
#define CQ 64
#define OQK 128             // fused q(64) + k(64)

// ---------------- scratch (device globals; no allocation allowed) -----------
__device__ float g_qk[(size_t)BB*NN*OQK];       //  qk_t[b][n][0..63]=q, [64..127]=k
__device__ float g_v [(size_t)BB*NN*CC];        //  v_t[b][n][c]
__device__ float g_eH[(size_t)BB*HH*WW*HH];     //  eH[b][h][w][i]
__device__ float g_eW[(size_t)BB*HH*WW*WW];     //  eW[b][h][w][j]
__device__ float g_oH[(size_t)BB*NN*CC];        //  oH[((b*W+w)*H+h)*C + c]
__device__ float g_m  [(size_t)BB*NN];          //  joint softmax max
__device__ float g_inv[(size_t)BB*NN];          //  joint softmax 1/sum
__device__ float g_Wqk[OQK*CC];
__device__ float g_bqk[OQK];

// ---------------- tf32 mma helpers ------------------------------------------
__device__ __forceinline__ uint32_t f2tf(float f) {
    uint32_t u;
    asm("cvt.rna.tf32.f32 %0, %1;" : "=r"(u) : "f"(f));
    return u;
}

__device__ __forceinline__ void mma_tf32(float c[4], const uint32_t a[4], const uint32_t b[2]) {
    asm volatile(
        "mma.sync.aligned.m16n8k8.row.col.f32.tf32.tf32.f32 "
        "{%0,%1,%2,%3}, {%4,%5,%6,%7}, {%8,%9}, {%0,%1,%2,%3};"
        : "+f"(c[0]), "+f"(c[1]), "+f"(c[2]), "+f"(c[3])
        : "r"(a[0]), "r"(a[1]), "r"(a[2]), "r"(a[3]), "r"(b[0]), "r"(b[1]));
}

__device__ __forceinline__ void split2(float v, uint32_t* hi, uint32_t* lo) {
    uint32_t h = f2tf(v);
    *hi = h;
    *lo = f2tf(v - __uint_as_float(h));
}

// ---------------- pack Wq,Wk -> combined ------------------------------------
__global__ void pack_wqk(const float* __restrict__ Wq, const float* __restrict__ bq,
                         const float* __restrict__ Wk, const float* __restrict__ bk)
{
    int i = blockIdx.x * blockDim.x + threadIdx.x;
    if (i < CQ*CC) {
        g_Wqk[i]          = Wq[i];
        g_Wqk[CQ*CC + i]  = Wk[i];
    }
    if (i < CQ) { g_bqk[i] = bq[i]; g_bqk[CQ + i] = bk[i]; }
}

// ---------------- TC GEMM (double-buffered, qk+v merged) --------------------
#define AS_STRIDE 136
#define BS_STRIDE 36
#define SMEM_GEMM ((2*32*AS_STRIDE + 2*128*BS_STRIDE) * 4)

__global__ __launch_bounds__(256)
void gemm_qkv_tc(const float* __restrict__ X, const float* __restrict__ Wv,
                 const float* __restrict__ bv)
{
    extern __shared__ uint32_t smem_u[];
    uint32_t* As = smem_u;                    // [2][32][136]  (k, m)
    uint32_t* Bs = smem_u + 2*32*AS_STRIDE;   // [2][128][36]  (o, k)

    const int bx = blockIdx.x;
    const int isV = (bx < 4);
    const int O = isV ? CC : OQK;
    const float* Wm   = isV ? Wv : g_Wqk;
    const float* bias = isV ? bv : g_bqk;
    float* outp       = isV ? g_v : g_qk;

    const int b  = blockIdx.z;
    const int n0 = blockIdx.y * 128;
    const int o0 = isV ? bx * 128 : 0;

    const int tid  = threadIdx.x;
    const int warp = tid >> 5, lane = tid & 31;
    const int g = lane >> 2, tig = lane & 3;
    const int wm = warp >> 2, wn = warp & 3;

    const float* Xp = X + (size_t)b*CC*NN + n0;
    const float* Wb = Wm + (size_t)o0*CC;

    const int col4 = tid & 31, krowA = tid >> 5;
    const int orow = tid >> 1, kcB = (tid & 1) * 16;

    float4 ar[4], br[4];
    #pragma unroll
    for (int it = 0; it < 4; it++) {
        ar[it] = *(const float4*)(Xp + (size_t)(krowA + it*8)*NN + col4*4);
        br[it] = *(const float4*)(Wb + (size_t)orow*CC + kcB + it*4);
    }
    {
        #pragma unroll
        for (int it = 0; it < 4; it++) {
            uint32_t* d = As + (krowA + it*8)*AS_STRIDE + col4*4;
            d[0]=f2tf(ar[it].x); d[1]=f2tf(ar[it].y); d[2]=f2tf(ar[it].z); d[3]=f2tf(ar[it].w);
            uint32_t* e = Bs + orow*BS_STRIDE + kcB + it*4;
            e[0]=f2tf(br[it].x); e[1]=f2tf(br[it].y); e[2]=f2tf(br[it].z); e[3]=f2tf(br[it].w);
        }
    }
    __syncthreads();

    float acc[4][4][4];
    #pragma unroll
    for (int i = 0; i < 4; i++)
        #pragma unroll
        for (int j = 0; j < 4; j++)
            #pragma unroll
            for (int r = 0; r < 4; r++) acc[i][j][r] = 0.f;

    for (int t = 0; t < 16; t++) {
        const int cur = t & 1;
        if (t < 15) {
            const int c1 = (t+1)*32;
            #pragma unroll
            for (int it = 0; it < 4; it++) {
                ar[it] = *(const float4*)(Xp + (size_t)(c1 + krowA + it*8)*NN + col4*4);
                br[it] = *(const float4*)(Wb + (size_t)orow*CC + c1 + kcB + it*4);
            }
        }
        const uint32_t* Ac = As + cur*32*AS_STRIDE;
        const uint32_t* Bc = Bs + cur*128*BS_STRIDE;
        #pragma unroll
        for (int k8 = 0; k8 < 32; k8 += 8) {
            uint32_t af[4][4], bf[4][2];
            #pragma unroll
            for (int mt = 0; mt < 4; mt++) {
                const int rb = wm*64 + mt*16;
                af[mt][0] = Ac[(k8+tig  )*AS_STRIDE + rb + g];
                af[mt][1] = Ac[(k8+tig  )*AS_STRIDE + rb + g + 8];
                af[mt][2] = Ac[(k8+tig+4)*AS_STRIDE + rb + g];
                af[mt][3] = Ac[(k8+tig+4)*AS_STRIDE + rb + g + 8];
            }
            #pragma unroll
            for (int nt = 0; nt < 4; nt++) {
                const int cb = wn*32 + nt*8 + g;
                bf[nt][0] = Bc[cb*BS_STRIDE + k8 + tig];
                bf[nt][1] = Bc[cb*BS_STRIDE + k8 + tig + 4];
            }
            #pragma unroll
            for (int mt = 0; mt < 4; mt++)
                #pragma unroll
                for (int nt = 0; nt < 4; nt++)
                    mma_tf32(acc[mt][nt], af[mt], bf[nt]);
        }
        if (t < 15) {
            uint32_t* Ab = As + (cur^1)*32*AS_STRIDE;
            uint32_t* Bb = Bs + (cur^1)*128*BS_STRIDE;
            #pragma unroll
            for (int it = 0; it < 4; it++) {
                uint32_t* d = Ab + (krowA + it*8)*AS_STRIDE + col4*4;
                d[0]=f2tf(ar[it].x); d[1]=f2tf(ar[it].y); d[2]=f2tf(ar[it].z); d[3]=f2tf(ar[it].w);
                uint32_t* e = Bb + orow*BS_STRIDE + kcB + it*4;
                e[0]=f2tf(br[it].x); e[1]=f2tf(br[it].y); e[2]=f2tf(br[it].z); e[3]=f2tf(br[it].w);
            }
        }
        __syncthreads();
    }

    #pragma unroll
    for (int mt = 0; mt < 4; mt++) {
        int row = n0 + wm*64 + mt*16 + g;
        #pragma unroll
        for (int nt = 0; nt < 4; nt++) {
            int col = o0 + wn*32 + nt*8 + tig*2;
            float b0 = bias[col], b1 = bias[col + 1];
            size_t base0 = ((size_t)b * NN + row) * O + col;
            size_t base1 = base0 + (size_t)8 * O;
            *(float2*)(outp + base0) = make_float2(acc[mt][nt][0] + b0, acc[mt][nt][1] + b1);
            *(float2*)(outp + base1) = make_float2(acc[mt][nt][2] + b0, acc[mt][nt][3] + b1);
        }
    }
}

// ---------------- TC energy: E = Q·K^T via split-tf32 (fp32 accurate) -------
// Block: 128(r) x 64(s) tile of one (b, f, branch); K = 64.
// Raw fp32 Q/K in smem; hi/lo split at fragment-load time.
#define EQ_S 68
#define SMEM_E ((128 + 64) * EQ_S * 4)

__global__ __launch_bounds__(256)
void energy_tc()
{
    extern __shared__ float esm[];
    float* Qf = esm;                  // [128][68]
    float* Kf = esm + 128*EQ_S;       // [64][68]

    const int isH = blockIdx.y >> 1;
    const int s0  = (blockIdx.y & 1) * 64;
    const int b = blockIdx.z, f = blockIdx.x;

    size_t qbase, obase; int rq, ro;
    if (isH) { qbase = ((size_t)b*NN + f) * OQK;            rq = WW*OQK;
               obase = (size_t)b*HH*WW*HH + (size_t)f*HH;   ro = WW*HH; }
    else     { qbase = ((size_t)b*NN + (size_t)f*WW) * OQK; rq = OQK;
               obase = (size_t)b*HH*WW*WW + (size_t)f*WW*WW; ro = WW; }
    float* outp = isH ? g_eH : g_eW;

    const int tid = threadIdx.x;
    // fill Q rows 0..127 (q half, cols 0..63)
    {
        const int row = tid & 127, ch = tid >> 7;
        const float* src = &g_qk[qbase + (size_t)row*rq + ch*32];
        #pragma unroll
        for (int i = 0; i < 8; i++)
            *(float4*)&Qf[row*EQ_S + ch*32 + i*4] = *(const float4*)(src + i*4);
    }
    // fill K rows s0..s0+63 (k half, cols 64..127)
    {
        const int row = tid & 63, cq = tid >> 6;
        const float* src = &g_qk[qbase + (size_t)(s0+row)*rq + 64 + cq*16];
        #pragma unroll
        for (int i = 0; i < 4; i++)
            *(float4*)&Kf[row*EQ_S + cq*16 + i*4] = *(const float4*)(src + i*4);
    }
    __syncthreads();

    const int warp = tid >> 5, lane = tid & 31;
    const int g = lane >> 2, tig = lane & 3;
    const int wm = warp >> 2, wn = warp & 3;   // 2 x 4 warps, warp tile 64 x 16

    float acc[4][2][4];
    #pragma unroll
    for (int i = 0; i < 4; i++)
        #pragma unroll
        for (int j = 0; j < 2; j++)
            #pragma unroll
            for (int r = 0; r < 4; r++) acc[i][j][r] = 0.f;

    #pragma unroll
    for (int k8 = 0; k8 < 64; k8 += 8) {
        uint32_t ah[4][4], al[4][4], bh[2][2], bl[2][2];
        #pragma unroll
        for (int mt = 0; mt < 4; mt++) {
            const int rb = wm*64 + mt*16;
            split2(Qf[(rb+g  )*EQ_S + k8+tig  ], &ah[mt][0], &al[mt][0]);
            split2(Qf[(rb+g+8)*EQ_S + k8+tig  ], &ah[mt][1], &al[mt][1]);
            split2(Qf[(rb+g  )*EQ_S + k8+tig+4], &ah[mt][2], &al[mt][2]);
            split2(Qf[(rb+g+8)*EQ_S + k8+tig+4], &ah[mt][3], &al[mt][3]);
        }
        #pragma unroll
        for (int nt = 0; nt < 2; nt++) {
            const int cb = wn*16 + nt*8 + g;
            split2(Kf[cb*EQ_S + k8+tig  ], &bh[nt][0], &bl[nt][0]);
            split2(Kf[cb*EQ_S + k8+tig+4], &bh[nt][1], &bl[nt][1]);
        }
        #pragma unroll
        for (int mt = 0; mt < 4; mt++)
            #pragma unroll
            for (int nt = 0; nt < 2; nt++) {
                mma_tf32(acc[mt][nt], ah[mt], bh[nt]);
                mma_tf32(acc[mt][nt], ah[mt], bl[nt]);
                mma_tf32(acc[mt][nt], al[mt], bh[nt]);
            }
    }

    #pragma unroll
    for (int mt = 0; mt < 4; mt++) {
        const int r0 = wm*64 + mt*16 + g, r1 = r0 + 8;
        #pragma unroll
        for (int nt = 0; nt < 2; nt++) {
            #pragma unroll
            for (int cc = 0; cc < 2; cc++) {
                const int s = s0 + wn*16 + nt*8 + tig*2 + cc;
                float v0 = acc[mt][nt][cc];
                float v1 = acc[mt][nt][2+cc];
                if (isH && r0 == s) v0 = -INFINITY;
                if (isH && r1 == s) v1 = -INFINITY;
                outp[obase + (size_t)r0 * ro + s] = v0;
                outp[obase + (size_t)r1 * ro + s] = v1;
            }
        }
    }
}

// ---------------- stats: joint softmax (m, 1/s) per pixel -------------------
__global__ void stats_kernel()
{
    int gwarp = (blockIdx.x * blockDim.x + threadIdx.x) >> 5;
    int lane  = threadIdx.x & 31;
    if (gwarp >= BB*HH*WW) return;

    float4 vH = ((const float4*)(g_eH + (size_t)gwarp * HH))[lane];
    float4 vW = ((const float4*)(g_eW + (size_t)gwarp * WW))[lane];

    float m = fmaxf(fmaxf(fmaxf(vH.x, vH.y), fmaxf(vH.z, vH.w)),
                    fmaxf(fmaxf(vW.x, vW.y), fmaxf(vW.z, vW.w)));
    #pragma unroll
    for (int off = 16; off; off >>= 1)
        m = fmaxf(m, __shfl_xor_sync(0xffffffffu, m, off));

    float s = __expf(vH.x - m) + __expf(vH.y - m) + __expf(vH.z - m) + __expf(vH.w - m)
            + __expf(vW.x - m) + __expf(vW.y - m) + __expf(vW.z - m) + __expf(vW.w - m);
    #pragma unroll
    for (int off = 16; off; off >>= 1)
        s += __shfl_xor_sync(0xffffffffu, s, off);

    if (lane == 0) { g_m[gwarp] = m; g_inv[gwarp] = 1.f / s; }
}

// ---------------- out GEMMs: p = exp(E-m)*inv applied at A-fill --------------
#define OAS 36
#define OVS 136

__global__ __launch_bounds__(256)
void out_h_kernel()
{
    __shared__ uint32_t As2[128][OAS];
    __shared__ uint32_t Vs[32][OVS];

    const int bz = blockIdx.y;
    const int b = bz >> 7, f = bz & 127;      // f = w
    const int c0 = blockIdx.x * 128;

    const size_t vbase = ((size_t)b*NN + f) * CC;
    const size_t kstr  = (size_t)WW*CC;
    const size_t abase = (size_t)b*HH*WW*HH + (size_t)f*HH;
    const int anstride = WW*HH;
    const size_t ob = (size_t)bz * 128 * CC;

    const int tid = threadIdx.x;
    const int warp = tid >> 5, lane = tid & 31;
    const int g = lane >> 2, tig = lane & 3;
    const int wm = warp >> 2, wn = warp & 3;

    float acc2[4][4][4];
    #pragma unroll
    for (int i = 0; i < 4; i++)
        #pragma unroll
        for (int j = 0; j < 4; j++)
            #pragma unroll
            for (int r = 0; r < 4; r++) acc2[i][j][r] = 0.f;

    const int nrow = tid >> 1, kcA = (tid & 1) * 16;
    const int krowB = tid >> 3, vc16 = (tid & 7) * 16;

    // softmax params for this thread's A row (row = h = nrow, pixel (b, nrow, f))
    const size_t pidx = (size_t)b*NN + (size_t)nrow*WW + f;
    const float sm_m = g_m[pidx], sm_i = g_inv[pidx];

    for (int k0 = 0; k0 < 128; k0 += 32) {
        #pragma unroll
        for (int it = 0; it < 4; it++) {
            float4 v = *(const float4*)(g_eH + abase + (size_t)nrow*anstride + k0 + kcA + it*4);
            uint32_t* d = &As2[nrow][kcA + it*4];
            d[0]=f2tf(__expf(v.x - sm_m)*sm_i); d[1]=f2tf(__expf(v.y - sm_m)*sm_i);
            d[2]=f2tf(__expf(v.z - sm_m)*sm_i); d[3]=f2tf(__expf(v.w - sm_m)*sm_i);
        }
        {
            const float* src = g_v + vbase + (size_t)(k0 + krowB)*kstr + c0 + vc16;
            uint32_t* d = &Vs[krowB][vc16];
            #pragma unroll
            for (int i = 0; i < 4; i++) {
                float4 v = *(const float4*)(src + i*4);
                d[i*4+0]=f2tf(v.x); d[i*4+1]=f2tf(v.y); d[i*4+2]=f2tf(v.z); d[i*4+3]=f2tf(v.w);
            }
        }
        __syncthreads();
        #pragma unroll
        for (int k8 = 0; k8 < 32; k8 += 8) {
            uint32_t af[4][4], bf[4][2];
            #pragma unroll
            for (int mt = 0; mt < 4; mt++) {
                const int rb = wm*64 + mt*16;
                af[mt][0] = As2[rb+g  ][k8+tig];
                af[mt][1] = As2[rb+g+8][k8+tig];
                af[mt][2] = As2[rb+g  ][k8+tig+4];
                af[mt][3] = As2[rb+g+8][k8+tig+4];
            }
            #pragma unroll
            for (int nt = 0; nt < 4; nt++) {
                const int cb = wn*32 + nt*8 + g;
                bf[nt][0] = Vs[k8+tig  ][cb];
                bf[nt][1] = Vs[k8+tig+4][cb];
            }
            #pragma unroll
            for (int mt = 0; mt < 4; mt++)
                #pragma unroll
                for (int nt = 0; nt < 4; nt++)
                    mma_tf32(acc2[mt][nt], af[mt], bf[nt]);
        }
        __syncthreads();
    }

    #pragma unroll
    for (int mt = 0; mt < 4; mt++) {
        const int row = wm*64 + mt*16 + g;
        #pragma unroll
        for (int nt = 0; nt < 4; nt++) {
            const int col = c0 + wn*32 + nt*8 + tig*2;
            *(float2*)(g_oH + ob + (size_t)row*CC + col) =
                make_float2(acc2[mt][nt][0], acc2[mt][nt][1]);
            *(float2*)(g_oH + ob + (size_t)(row+8)*CC + col) =
                make_float2(acc2[mt][nt][2], acc2[mt][nt][3]);
        }
    }
}

// ---------------- W branch + fused combine (final output) -------------------
__global__ __launch_bounds__(256)
void out_w_kernel(const float* __restrict__ x, const float* __restrict__ gamma,
                  float* __restrict__ out)
{
    __shared__ uint32_t As2[128][OAS];
    __shared__ uint32_t Vs[32][OVS];

    const int bz = blockIdx.y;
    const int b = bz >> 7, f = bz & 127;      // f = h
    const int c0 = blockIdx.x * 128;

    const size_t vbase = ((size_t)b*NN + (size_t)f*WW) * CC;
    const size_t kstr  = CC;
    const size_t abase = (size_t)b*HH*WW*WW + (size_t)f*WW*WW;
    const int anstride = WW;

    const int tid = threadIdx.x;
    const int warp = tid >> 5, lane = tid & 31;
    const int g = lane >> 2, tig = lane & 3;
    const int wm = warp >> 2, wn = warp & 3;

    float acc2[4][4][4];
    #pragma unroll
    for (int i = 0; i < 4; i++)
        #pragma unroll
        for (int j = 0; j < 4; j++)
            #pragma unroll
            for (int r = 0; r < 4; r++) acc2[i][j][r] = 0.f;

    const int nrow = tid >> 1, kcA = (tid & 1) * 16;
    const int krowB = tid >> 3, vc16 = (tid & 7) * 16;

    // softmax params for this thread's A row (row = w = nrow, pixel (b, f, nrow))
    const size_t pidx = (size_t)b*NN + (size_t)f*WW + nrow;
    const float sm_m = g_m[pidx], sm_i = g_inv[pidx];

    for (int k0 = 0; k0 < 128; k0 += 32) {
        #pragma unroll
        for (int it = 0; it < 4; it++) {
            float4 v = *(const float4*)(g_eW + abase + (size_t)nrow*anstride + k0 + kcA + it*4);
            uint32_t* d = &As2[nrow][kcA + it*4];
            d[0]=f2tf(__expf(v.x - sm_m)*sm_i); d[1]=f2tf(__expf(v.y - sm_m)*sm_i);
            d[2]=f2tf(__expf(v.z - sm_m)*sm_i); d[3]=f2tf(__expf(v.w - sm_m)*sm_i);
        }
        {
            const float* src = g_v + vbase + (size_t)(k0 + krowB)*kstr + c0 + vc16;
            uint32_t* d = &Vs[krowB][vc16];
            #pragma unroll
            for (int i = 0; i < 4; i++) {
                float4 v = *(const float4*)(src + i*4);
                d[i*4+0]=f2tf(v.x); d[i*4+1]=f2tf(v.y); d[i*4+2]=f2tf(v.z); d[i*4+3]=f2tf(v.w);
            }
        }
        __syncthreads();
        #pragma unroll
        for (int k8 = 0; k8 < 32; k8 += 8) {
            uint32_t af[4][4], bf[4][2];
            #pragma unroll
            for (int mt = 0; mt < 4; mt++) {
                const int rb = wm*64 + mt*16;
                af[mt][0] = As2[rb+g  ][k8+tig];
                af[mt][1] = As2[rb+g+8][k8+tig];
                af[mt][2] = As2[rb+g  ][k8+tig+4];
                af[mt][3] = As2[rb+g+8][k8+tig+4];
            }
            #pragma unroll
            for (int nt = 0; nt < 4; nt++) {
                const int cb = wn*32 + nt*8 + g;
                bf[nt][0] = Vs[k8+tig  ][cb];
                bf[nt][1] = Vs[k8+tig+4][cb];
            }
            #pragma unroll
            for (int mt = 0; mt < 4; mt++)
                #pragma unroll
                for (int nt = 0; nt < 4; nt++)
                    mma_tf32(acc2[mt][nt], af[mt], bf[nt]);
        }
        __syncthreads();
    }

    // fused epilogue: out[b][c][f][w] = gamma*(accW[w][c] + oH[b][w][f][c]) + x
    float (*T)[136] = reinterpret_cast<float(*)[136]>(&As2[0][0]);
    float (*O)[33]  = reinterpret_cast<float(*)[33]>(&Vs[0][0]);
    const float gm = gamma[0];

    const int orow = tid >> 1, olc = (tid & 1) * 16;  // oH strip load
    const int wlc = tid >> 3, wwo = (tid & 7) * 16;   // out write

    for (int s = 0; s < 4; s++) {
        __syncthreads();
        {
            const float* src = g_oH + (((size_t)(b*128 + orow))*128 + f)*CC + c0 + s*32 + olc;
            #pragma unroll
            for (int i = 0; i < 4; i++) {
                float4 v = *(const float4*)(src + i*4);
                O[orow][olc+i*4+0]=v.x; O[orow][olc+i*4+1]=v.y;
                O[orow][olc+i*4+2]=v.z; O[orow][olc+i*4+3]=v.w;
            }
        }
        if (wn == s) {
            #pragma unroll
            for (int mt = 0; mt < 4; mt++) {
                const int row = wm*64 + mt*16 + g;
                #pragma unroll
                for (int nt = 0; nt < 4; nt++) {
                    const int lc = nt*8 + tig*2;
                    T[lc  ][row]   = acc2[mt][nt][0];
                    T[lc+1][row]   = acc2[mt][nt][1];
                    T[lc  ][row+8] = acc2[mt][nt][2];
                    T[lc+1][row+8] = acc2[mt][nt][3];
                }
            }
        }
        __syncthreads();
        {
            const int c = c0 + s*32 + wlc;
            const size_t xb = (((size_t)b*CC + c)*HH + f)*WW;
            #pragma unroll
            for (int i = 0; i < 4; i++) {
                const int w = wwo + i*4;
                float4 xv = *(const float4*)(x + xb + w);
                float4 o;
                o.x = gm*(T[wlc][w+0] + O[w+0][wlc]) + xv.x;
                o.y = gm*(T[wlc][w+1] + O[w+1][wlc]) + xv.y;
                o.z = gm*(T[wlc][w+2] + O[w+2][wlc]) + xv.z;
                o.w = gm*(T[wlc][w+3] + O[w+3][wlc]) + xv.w;
                *(float4*)(out + xb + w) = o;
            }
        }
    }
}

// ---------------- launch -----------------------------------------------------
extern "C" void kernel_launch(void* const* d_in, const int* in_sizes, int n_in,
                              void* d_out, int out_size)
{
    const float* x     = (const float*)d_in[0];
    const float* Wq    = (const float*)d_in[1];
    const float* bq    = (const float*)d_in[2];
    const float* Wk    = (const float*)d_in[3];
    const float* bk    = (const float*)d_in[4];
    const float* Wv    = (const float*)d_in[5];
    const float* bv    = (const float*)d_in[6];
    const float* gamma = (const float*)d_in[7];
    float* out = (float*)d_out;

    cudaFuncSetAttribute(gemm_qkv_tc, cudaFuncAttributeMaxDynamicSharedMemorySize, SMEM_GEMM);
    cudaFuncSetAttribute(energy_tc,   cudaFuncAttributeMaxDynamicSharedMemorySize, SMEM_E);

    // 0) pack q/k weights
    pack_wqk<<<128, 256>>>(Wq, bq, Wk, bk);

    // 1) qk + v projections in one launch (x tile 4 = qk, tiles 0-3 = v)
    gemm_qkv_tc<<<dim3(5, NN/128, BB), 256, SMEM_GEMM>>>(x, Wv, bv);

    // 2) energies via split-tf32 tensor cores, both branches
    energy_tc<<<dim3(128, 4, BB), 256, SMEM_E>>>();

    // 3) joint softmax stats (m, 1/s) only — no E rewrite
    stats_kernel<<<(BB*HH*WW*32 + 255) / 256, 256>>>();

    // 4) H-branch p@V -> g_oH (p computed inline from raw E)
    out_h_kernel<<<dim3(CC/128, BB*128), 256>>>();
    // 5) W-branch p@V + fused combine -> out
    out_w_kernel<<<dim3(CC/128, BB*128), 256>>>(x, gamma, out);
}

// round 7
// speedup vs baseline: 1.2226x; 1.0016x over previous
#include <cuda_runtime.h>
#include <math.h>
#include <stdint.h>

// Problem constants
#define BB 4
#define CC 512
#define HH 128
#define WW 128
#define NN (HH*WW)          // 16384
#define CQ 64
#define OQK 128             // fused q(64) + k(64)

// ---------------- scratch (device globals; no allocation allowed) -----------
__device__ float g_qk[(size_t)BB*NN*OQK];       //  qk_t[b][n][0..63]=q, [64..127]=k
__device__ float g_v [(size_t)BB*NN*CC];        //  v_t[b][n][c]
__device__ float g_eH[(size_t)BB*HH*WW*HH];     //  eH[b][h][w][i]
__device__ float g_eW[(size_t)BB*HH*WW*WW];     //  eW[b][h][w][j]
__device__ float g_oH[(size_t)BB*NN*CC];        //  oH[((b*W+w)*H+h)*C + c]
__device__ float g_m  [(size_t)BB*NN];          //  joint softmax max
__device__ float g_inv[(size_t)BB*NN];          //  joint softmax 1/sum
__device__ float g_Wqk[OQK*CC];
__device__ float g_bqk[OQK];

// ---------------- tf32 mma helpers ------------------------------------------
__device__ __forceinline__ uint32_t f2tf(float f) {
    uint32_t u;
    asm("cvt.rna.tf32.f32 %0, %1;" : "=r"(u) : "f"(f));
    return u;
}

__device__ __forceinline__ void mma_tf32(float c[4], const uint32_t a[4], const uint32_t b[2]) {
    asm volatile(
        "mma.sync.aligned.m16n8k8.row.col.f32.tf32.tf32.f32 "
        "{%0,%1,%2,%3}, {%4,%5,%6,%7}, {%8,%9}, {%0,%1,%2,%3};"
        : "+f"(c[0]), "+f"(c[1]), "+f"(c[2]), "+f"(c[3])
        : "r"(a[0]), "r"(a[1]), "r"(a[2]), "r"(a[3]), "r"(b[0]), "r"(b[1]));
}

__device__ __forceinline__ void split2(float v, uint32_t* hi, uint32_t* lo) {
    uint32_t h = f2tf(v);
    *hi = h;
    *lo = f2tf(v - __uint_as_float(h));
}

// ---------------- pack Wq,Wk -> combined ------------------------------------
__global__ void pack_wqk(const float* __restrict__ Wq, const float* __restrict__ bq,
                         const float* __restrict__ Wk, const float* __restrict__ bk)
{
    int i = blockIdx.x * blockDim.x + threadIdx.x;
    if (i < CQ*CC) {
        g_Wqk[i]          = Wq[i];
        g_Wqk[CQ*CC + i]  = Wk[i];
    }
    if (i < CQ) { g_bqk[i] = bq[i]; g_bqk[CQ + i] = bk[i]; }
}

// ---------------- TC GEMM (double-buffered, qk+v merged) --------------------
#define AS_STRIDE 136
#define BS_STRIDE 36
#define SMEM_GEMM ((2*32*AS_STRIDE + 2*128*BS_STRIDE) * 4)

__global__ __launch_bounds__(256)
void gemm_qkv_tc(const float* __restrict__ X, const float* __restrict__ Wv,
                 const float* __restrict__ bv)
{
    extern __shared__ uint32_t smem_u[];
    uint32_t* As = smem_u;                    // [2][32][136]  (k, m)
    uint32_t* Bs = smem_u + 2*32*AS_STRIDE;   // [2][128][36]  (o, k)

    const int bx = blockIdx.x;
    const int isV = (bx < 4);
    const int O = isV ? CC : OQK;
    const float* Wm   = isV ? Wv : g_Wqk;
    const float* bias = isV ? bv : g_bqk;
    float* outp       = isV ? g_v : g_qk;

    const int b  = blockIdx.z;
    const int n0 = blockIdx.y * 128;
    const int o0 = isV ? bx * 128 : 0;

    const int tid  = threadIdx.x;
    const int warp = tid >> 5, lane = tid & 31;
    const int g = lane >> 2, tig = lane & 3;
    const int wm = warp >> 2, wn = warp & 3;

    const float* Xp = X + (size_t)b*CC*NN + n0;
    const float* Wb = Wm + (size_t)o0*CC;

    const int col4 = tid & 31, krowA = tid >> 5;
    const int orow = tid >> 1, kcB = (tid & 1) * 16;

    float4 ar[4], br[4];
    #pragma unroll
    for (int it = 0; it < 4; it++) {
        ar[it] = *(const float4*)(Xp + (size_t)(krowA + it*8)*NN + col4*4);
        br[it] = *(const float4*)(Wb + (size_t)orow*CC + kcB + it*4);
    }
    {
        #pragma unroll
        for (int it = 0; it < 4; it++) {
            uint32_t* d = As + (krowA + it*8)*AS_STRIDE + col4*4;
            d[0]=f2tf(ar[it].x); d[1]=f2tf(ar[it].y); d[2]=f2tf(ar[it].z); d[3]=f2tf(ar[it].w);
            uint32_t* e = Bs + orow*BS_STRIDE + kcB + it*4;
            e[0]=f2tf(br[it].x); e[1]=f2tf(br[it].y); e[2]=f2tf(br[it].z); e[3]=f2tf(br[it].w);
        }
    }
    __syncthreads();

    float acc[4][4][4];
    #pragma unroll
    for (int i = 0; i < 4; i++)
        #pragma unroll
        for (int j = 0; j < 4; j++)
            #pragma unroll
            for (int r = 0; r < 4; r++) acc[i][j][r] = 0.f;

    for (int t = 0; t < 16; t++) {
        const int cur = t & 1;
        if (t < 15) {
            const int c1 = (t+1)*32;
            #pragma unroll
            for (int it = 0; it < 4; it++) {
                ar[it] = *(const float4*)(Xp + (size_t)(c1 + krowA + it*8)*NN + col4*4);
                br[it] = *(const float4*)(Wb + (size_t)orow*CC + c1 + kcB + it*4);
            }
        }
        const uint32_t* Ac = As + cur*32*AS_STRIDE;
        const uint32_t* Bc = Bs + cur*128*BS_STRIDE;
        #pragma unroll
        for (int k8 = 0; k8 < 32; k8 += 8) {
            uint32_t af[4][4], bf[4][2];
            #pragma unroll
            for (int mt = 0; mt < 4; mt++) {
                const int rb = wm*64 + mt*16;
                af[mt][0] = Ac[(k8+tig  )*AS_STRIDE + rb + g];
                af[mt][1] = Ac[(k8+tig  )*AS_STRIDE + rb + g + 8];
                af[mt][2] = Ac[(k8+tig+4)*AS_STRIDE + rb + g];
                af[mt][3] = Ac[(k8+tig+4)*AS_STRIDE + rb + g + 8];
            }
            #pragma unroll
            for (int nt = 0; nt < 4; nt++) {
                const int cb = wn*32 + nt*8 + g;
                bf[nt][0] = Bc[cb*BS_STRIDE + k8 + tig];
                bf[nt][1] = Bc[cb*BS_STRIDE + k8 + tig + 4];
            }
            #pragma unroll
            for (int mt = 0; mt < 4; mt++)
                #pragma unroll
                for (int nt = 0; nt < 4; nt++)
                    mma_tf32(acc[mt][nt], af[mt], bf[nt]);
        }
        if (t < 15) {
            uint32_t* Ab = As + (cur^1)*32*AS_STRIDE;
            uint32_t* Bb = Bs + (cur^1)*128*BS_STRIDE;
            #pragma unroll
            for (int it = 0; it < 4; it++) {
                uint32_t* d = Ab + (krowA + it*8)*AS_STRIDE + col4*4;
                d[0]=f2tf(ar[it].x); d[1]=f2tf(ar[it].y); d[2]=f2tf(ar[it].z); d[3]=f2tf(ar[it].w);
                uint32_t* e = Bb + orow*BS_STRIDE + kcB + it*4;
                e[0]=f2tf(br[it].x); e[1]=f2tf(br[it].y); e[2]=f2tf(br[it].z); e[3]=f2tf(br[it].w);
            }
        }
        __syncthreads();
    }

    #pragma unroll
    for (int mt = 0; mt < 4; mt++) {
        int row = n0 + wm*64 + mt*16 + g;
        #pragma unroll
        for (int nt = 0; nt < 4; nt++) {
            int col = o0 + wn*32 + nt*8 + tig*2;
            float b0 = bias[col], b1 = bias[col + 1];
            size_t base0 = ((size_t)b * NN + row) * O + col;
            size_t base1 = base0 + (size_t)8 * O;
            *(float2*)(outp + base0) = make_float2(acc[mt][nt][0] + b0, acc[mt][nt][1] + b1);
            *(float2*)(outp + base1) = make_float2(acc[mt][nt][2] + b0, acc[mt][nt][3] + b1);
        }
    }
}

// ---------------- TC energy: E = Q·K^T via split-tf32 (fp32 accurate) -------
// Block: 128(r) x 64(s) tile of one (b, f, branch); K = 64.
// Raw fp32 Q/K in smem; hi/lo split at fragment-load time.
#define EQ_S 68
#define SMEM_E ((128 + 64) * EQ_S * 4)

__global__ __launch_bounds__(256)
void energy_tc()
{
    extern __shared__ float esm[];
    float* Qf = esm;                  // [128][68]
    float* Kf = esm + 128*EQ_S;       // [64][68]

    const int isH = blockIdx.y >> 1;
    const int s0  = (blockIdx.y & 1) * 64;
    const int b = blockIdx.z, f = blockIdx.x;

    size_t qbase, obase; int rq, ro;
    if (isH) { qbase = ((size_t)b*NN + f) * OQK;            rq = WW*OQK;
               obase = (size_t)b*HH*WW*HH + (size_t)f*HH;   ro = WW*HH; }
    else     { qbase = ((size_t)b*NN + (size_t)f*WW) * OQK; rq = OQK;
               obase = (size_t)b*HH*WW*WW + (size_t)f*WW*WW; ro = WW; }
    float* outp = isH ? g_eH : g_eW;

    const int tid = threadIdx.x;
    // fill Q rows 0..127 (q half, cols 0..63)
    {
        const int row = tid & 127, ch = tid >> 7;
        const float* src = &g_qk[qbase + (size_t)row*rq + ch*32];
        #pragma unroll
        for (int i = 0; i < 8; i++)
            *(float4*)&Qf[row*EQ_S + ch*32 + i*4] = *(const float4*)(src + i*4);
    }
    // fill K rows s0..s0+63 (k half, cols 64..127)
    {
        const int row = tid & 63, cq = tid >> 6;
        const float* src = &g_qk[qbase + (size_t)(s0+row)*rq + 64 + cq*16];
        #pragma unroll
        for (int i = 0; i < 4; i++)
            *(float4*)&Kf[row*EQ_S + cq*16 + i*4] = *(const float4*)(src + i*4);
    }
    __syncthreads();

    const int warp = tid >> 5, lane = tid & 31;
    const int g = lane >> 2, tig = lane & 3;
    const int wm = warp >> 2, wn = warp & 3;   // 2 x 4 warps, warp tile 64 x 16

    float acc[4][2][4];
    #pragma unroll
    for (int i = 0; i < 4; i++)
        #pragma unroll
        for (int j = 0; j < 2; j++)
            #pragma unroll
            for (int r = 0; r < 4; r++) acc[i][j][r] = 0.f;

    #pragma unroll
    for (int k8 = 0; k8 < 64; k8 += 8) {
        uint32_t ah[4][4], al[4][4], bh[2][2], bl[2][2];
        #pragma unroll
        for (int mt = 0; mt < 4; mt++) {
            const int rb = wm*64 + mt*16;
            split2(Qf[(rb+g  )*EQ_S + k8+tig  ], &ah[mt][0], &al[mt][0]);
            split2(Qf[(rb+g+8)*EQ_S + k8+tig  ], &ah[mt][1], &al[mt][1]);
            split2(Qf[(rb+g  )*EQ_S + k8+tig+4], &ah[mt][2], &al[mt][2]);
            split2(Qf[(rb+g+8)*EQ_S + k8+tig+4], &ah[mt][3], &al[mt][3]);
        }
        #pragma unroll
        for (int nt = 0; nt < 2; nt++) {
            const int cb = wn*16 + nt*8 + g;
            split2(Kf[cb*EQ_S + k8+tig  ], &bh[nt][0], &bl[nt][0]);
            split2(Kf[cb*EQ_S + k8+tig+4], &bh[nt][1], &bl[nt][1]);
        }
        #pragma unroll
        for (int mt = 0; mt < 4; mt++)
            #pragma unroll
            for (int nt = 0; nt < 2; nt++) {
                mma_tf32(acc[mt][nt], ah[mt], bh[nt]);
                mma_tf32(acc[mt][nt], ah[mt], bl[nt]);
                mma_tf32(acc[mt][nt], al[mt], bh[nt]);
            }
    }

    #pragma unroll
    for (int mt = 0; mt < 4; mt++) {
        const int r0 = wm*64 + mt*16 + g, r1 = r0 + 8;
        #pragma unroll
        for (int nt = 0; nt < 2; nt++) {
            #pragma unroll
            for (int cc = 0; cc < 2; cc++) {
                const int s = s0 + wn*16 + nt*8 + tig*2 + cc;
                float v0 = acc[mt][nt][cc];
                float v1 = acc[mt][nt][2+cc];
                if (isH && r0 == s) v0 = -INFINITY;
                if (isH && r1 == s) v1 = -INFINITY;
                outp[obase + (size_t)r0 * ro + s] = v0;
                outp[obase + (size_t)r1 * ro + s] = v1;
            }
        }
    }
}

// ---------------- stats: joint softmax (m, 1/s) per pixel -------------------
__global__ void stats_kernel()
{
    int gwarp = (blockIdx.x * blockDim.x + threadIdx.x) >> 5;
    int lane  = threadIdx.x & 31;
    if (gwarp >= BB*HH*WW) return;

    float4 vH = ((const float4*)(g_eH + (size_t)gwarp * HH))[lane];
    float4 vW = ((const float4*)(g_eW + (size_t)gwarp * WW))[lane];

    float m = fmaxf(fmaxf(fmaxf(vH.x, vH.y), fmaxf(vH.z, vH.w)),
                    fmaxf(fmaxf(vW.x, vW.y), fmaxf(vW.z, vW.w)));
    #pragma unroll
    for (int off = 16; off; off >>= 1)
        m = fmaxf(m, __shfl_xor_sync(0xffffffffu, m, off));

    float s = __expf(vH.x - m) + __expf(vH.y - m) + __expf(vH.z - m) + __expf(vH.w - m)
            + __expf(vW.x - m) + __expf(vW.y - m) + __expf(vW.z - m) + __expf(vW.w - m);
    #pragma unroll
    for (int off = 16; off; off >>= 1)
        s += __shfl_xor_sync(0xffffffffu, s, off);

    if (lane == 0) { g_m[gwarp] = m; g_inv[gwarp] = 1.f / s; }
}

// ---------------- out GEMMs: p = exp(E-m)*inv applied at A-fill --------------
#define OAS 36
#define OVS 136

__global__ __launch_bounds__(256)
void out_h_kernel()
{
    __shared__ uint32_t As2[128][OAS];
    __shared__ uint32_t Vs[32][OVS];

    const int bz = blockIdx.y;
    const int b = bz >> 7, f = bz & 127;      // f = w
    const int c0 = blockIdx.x * 128;

    const size_t vbase = ((size_t)b*NN + f) * CC;
    const size_t kstr  = (size_t)WW*CC;
    const size_t abase = (size_t)b*HH*WW*HH + (size_t)f*HH;
    const int anstride = WW*HH;
    const size_t ob = (size_t)bz * 128 * CC;

    const int tid = threadIdx.x;
    const int warp = tid >> 5, lane = tid & 31;
    const int g = lane >> 2, tig = lane & 3;
    const int wm = warp >> 2, wn = warp & 3;

    float acc2[4][4][4];
    #pragma unroll
    for (int i = 0; i < 4; i++)
        #pragma unroll
        for (int j = 0; j < 4; j++)
            #pragma unroll
            for (int r = 0; r < 4; r++) acc2[i][j][r] = 0.f;

    const int nrow = tid >> 1, kcA = (tid & 1) * 16;
    const int krowB = tid >> 3, vc16 = (tid & 7) * 16;

    // softmax params for this thread's A row (row = h = nrow, pixel (b, nrow, f))
    const size_t pidx = (size_t)b*NN + (size_t)nrow*WW + f;
    const float sm_m = g_m[pidx], sm_i = g_inv[pidx];

    for (int k0 = 0; k0 < 128; k0 += 32) {
        #pragma unroll
        for (int it = 0; it < 4; it++) {
            float4 v = *(const float4*)(g_eH + abase + (size_t)nrow*anstride + k0 + kcA + it*4);
            uint32_t* d = &As2[nrow][kcA + it*4];
            d[0]=f2tf(__expf(v.x - sm_m)*sm_i); d[1]=f2tf(__expf(v.y - sm_m)*sm_i);
            d[2]=f2tf(__expf(v.z - sm_m)*sm_i); d[3]=f2tf(__expf(v.w - sm_m)*sm_i);
        }
        {
            const float* src = g_v + vbase + (size_t)(k0 + krowB)*kstr + c0 + vc16;
            uint32_t* d = &Vs[krowB][vc16];
            #pragma unroll
            for (int i = 0; i < 4; i++) {
                float4 v = *(const float4*)(src + i*4);
                d[i*4+0]=f2tf(v.x); d[i*4+1]=f2tf(v.y); d[i*4+2]=f2tf(v.z); d[i*4+3]=f2tf(v.w);
            }
        }
        __syncthreads();
        #pragma unroll
        for (int k8 = 0; k8 < 32; k8 += 8) {
            uint32_t af[4][4], bf[4][2];
            #pragma unroll
            for (int mt = 0; mt < 4; mt++) {
                const int rb = wm*64 + mt*16;
                af[mt][0] = As2[rb+g  ][k8+tig];
                af[mt][1] = As2[rb+g+8][k8+tig];
                af[mt][2] = As2[rb+g  ][k8+tig+4];
                af[mt][3] = As2[rb+g+8][k8+tig+4];
            }
            #pragma unroll
            for (int nt = 0; nt < 4; nt++) {
                const int cb = wn*32 + nt*8 + g;
                bf[nt][0] = Vs[k8+tig  ][cb];
                bf[nt][1] = Vs[k8+tig+4][cb];
            }
            #pragma unroll
            for (int mt = 0; mt < 4; mt++)
                #pragma unroll
                for (int nt = 0; nt < 4; nt++)
                    mma_tf32(acc2[mt][nt], af[mt], bf[nt]);
        }
        __syncthreads();
    }

    #pragma unroll
    for (int mt = 0; mt < 4; mt++) {
        const int row = wm*64 + mt*16 + g;
        #pragma unroll
        for (int nt = 0; nt < 4; nt++) {
            const int col = c0 + wn*32 + nt*8 + tig*2;
            *(float2*)(g_oH + ob + (size_t)row*CC + col) =
                make_float2(acc2[mt][nt][0], acc2[mt][nt][1]);
            *(float2*)(g_oH + ob + (size_t)(row+8)*CC + col) =
                make_float2(acc2[mt][nt][2], acc2[mt][nt][3]);
        }
    }
}

// ---------------- W branch + fused combine (final output) -------------------
__global__ __launch_bounds__(256)
void out_w_kernel(const float* __restrict__ x, const float* __restrict__ gamma,
                  float* __restrict__ out)
{
    __shared__ uint32_t As2[128][OAS];
    __shared__ uint32_t Vs[32][OVS];

    const int bz = blockIdx.y;
    const int b = bz >> 7, f = bz & 127;      // f = h
    const int c0 = blockIdx.x * 128;

    const size_t vbase = ((size_t)b*NN + (size_t)f*WW) * CC;
    const size_t kstr  = CC;
    const size_t abase = (size_t)b*HH*WW*WW + (size_t)f*WW*WW;
    const int anstride = WW;

    const int tid = threadIdx.x;
    const int warp = tid >> 5, lane = tid & 31;
    const int g = lane >> 2, tig = lane & 3;
    const int wm = warp >> 2, wn = warp & 3;

    float acc2[4][4][4];
    #pragma unroll
    for (int i = 0; i < 4; i++)
        #pragma unroll
        for (int j = 0; j < 4; j++)
            #pragma unroll
            for (int r = 0; r < 4; r++) acc2[i][j][r] = 0.f;

    const int nrow = tid >> 1, kcA = (tid & 1) * 16;
    const int krowB = tid >> 3, vc16 = (tid & 7) * 16;

    // softmax params for this thread's A row (row = w = nrow, pixel (b, f, nrow))
    const size_t pidx = (size_t)b*NN + (size_t)f*WW + nrow;
    const float sm_m = g_m[pidx], sm_i = g_inv[pidx];

    for (int k0 = 0; k0 < 128; k0 += 32) {
        #pragma unroll
        for (int it = 0; it < 4; it++) {
            float4 v = *(const float4*)(g_eW + abase + (size_t)nrow*anstride + k0 + kcA + it*4);
            uint32_t* d = &As2[nrow][kcA + it*4];
            d[0]=f2tf(__expf(v.x - sm_m)*sm_i); d[1]=f2tf(__expf(v.y - sm_m)*sm_i);
            d[2]=f2tf(__expf(v.z - sm_m)*sm_i); d[3]=f2tf(__expf(v.w - sm_m)*sm_i);
        }
        {
            const float* src = g_v + vbase + (size_t)(k0 + krowB)*kstr + c0 + vc16;
            uint32_t* d = &Vs[krowB][vc16];
            #pragma unroll
            for (int i = 0; i < 4; i++) {
                float4 v = *(const float4*)(src + i*4);
                d[i*4+0]=f2tf(v.x); d[i*4+1]=f2tf(v.y); d[i*4+2]=f2tf(v.z); d[i*4+3]=f2tf(v.w);
            }
        }
        __syncthreads();
        #pragma unroll
        for (int k8 = 0; k8 < 32; k8 += 8) {
            uint32_t af[4][4], bf[4][2];
            #pragma unroll
            for (int mt = 0; mt < 4; mt++) {
                const int rb = wm*64 + mt*16;
                af[mt][0] = As2[rb+g  ][k8+tig];
                af[mt][1] = As2[rb+g+8][k8+tig];
                af[mt][2] = As2[rb+g  ][k8+tig+4];
                af[mt][3] = As2[rb+g+8][k8+tig+4];
            }
            #pragma unroll
            for (int nt = 0; nt < 4; nt++) {
                const int cb = wn*32 + nt*8 + g;
                bf[nt][0] = Vs[k8+tig  ][cb];
                bf[nt][1] = Vs[k8+tig+4][cb];
            }
            #pragma unroll
            for (int mt = 0; mt < 4; mt++)
                #pragma unroll
                for (int nt = 0; nt < 4; nt++)
                    mma_tf32(acc2[mt][nt], af[mt], bf[nt]);
        }
        __syncthreads();
    }

    // fused epilogue: out[b][c][f][w] = gamma*(accW[w][c] + oH[b][w][f][c]) + x
    float (*T)[136] = reinterpret_cast<float(*)[136]>(&As2[0][0]);
    float (*O)[33]  = reinterpret_cast<float(*)[33]>(&Vs[0][0]);
    const float gm = gamma[0];

    const int orow = tid >> 1, olc = (tid & 1) * 16;  // oH strip load
    const int wlc = tid >> 3, wwo = (tid & 7) * 16;   // out write

    for (int s = 0; s < 4; s++) {
        __syncthreads();
        {
            const float* src = g_oH + (((size_t)(b*128 + orow))*128 + f)*CC + c0 + s*32 + olc;
            #pragma unroll
            for (int i = 0; i < 4; i++) {
                float4 v = *(const float4*)(src + i*4);
                O[orow][olc+i*4+0]=v.x; O[orow][olc+i*4+1]=v.y;
                O[orow][olc+i*4+2]=v.z; O[orow][olc+i*4+3]=v.w;
            }
        }
        if (wn == s) {
            #pragma unroll
            for (int mt = 0; mt < 4; mt++) {
                const int row = wm*64 + mt*16 + g;
                #pragma unroll
                for (int nt = 0; nt < 4; nt++) {
                    const int lc = nt*8 + tig*2;
                    T[lc  ][row]   = acc2[mt][nt][0];
                    T[lc+1][row]   = acc2[mt][nt][1];
                    T[lc  ][row+8] = acc2[mt][nt][2];
                    T[lc+1][row+8] = acc2[mt][nt][3];
                }
            }
        }
        __syncthreads();
        {
            const int c = c0 + s*32 + wlc;
            const size_t xb = (((size_t)b*CC + c)*HH + f)*WW;
            #pragma unroll
            for (int i = 0; i < 4; i++) {
                const int w = wwo + i*4;
                float4 xv = *(const float4*)(x + xb + w);
                float4 o;
                o.x = gm*(T[wlc][w+0] + O[w+0][wlc]) + xv.x;
                o.y = gm*(T[wlc][w+1] + O[w+1][wlc]) + xv.y;
                o.z = gm*(T[wlc][w+2] + O[w+2][wlc]) + xv.z;
                o.w = gm*(T[wlc][w+3] + O[w+3][wlc]) + xv.w;
                *(float4*)(out + xb + w) = o;
            }
        }
    }
}

// ---------------- launch -----------------------------------------------------
extern "C" void kernel_launch(void* const* d_in, const int* in_sizes, int n_in,
                              void* d_out, int out_size)
{
    const float* x     = (const float*)d_in[0];
    const float* Wq    = (const float*)d_in[1];
    const float* bq    = (const float*)d_in[2];
    const float* Wk    = (const float*)d_in[3];
    const float* bk    = (const float*)d_in[4];
    const float* Wv    = (const float*)d_in[5];
    const float* bv    = (const float*)d_in[6];
    const float* gamma = (const float*)d_in[7];
    float* out = (float*)d_out;

    cudaFuncSetAttribute(gemm_qkv_tc, cudaFuncAttributeMaxDynamicSharedMemorySize, SMEM_GEMM);
    cudaFuncSetAttribute(energy_tc,   cudaFuncAttributeMaxDynamicSharedMemorySize, SMEM_E);

    // 0) pack q/k weights
    pack_wqk<<<128, 256>>>(Wq, bq, Wk, bk);

    // 1) qk + v projections in one launch (x tile 4 = qk, tiles 0-3 = v)
    gemm_qkv_tc<<<dim3(5, NN/128, BB), 256, SMEM_GEMM>>>(x, Wv, bv);

    // 2) energies via split-tf32 tensor cores, both branches
    energy_tc<<<dim3(128, 4, BB), 256, SMEM_E>>>();

    // 3) joint softmax stats (m, 1/s) only — no E rewrite
    stats_kernel<<<(BB*HH*WW*32 + 255) / 256, 256>>>();

    // 4) H-branch p@V -> g_oH (p computed inline from raw E)
    out_h_kernel<<<dim3(CC/128, BB*128), 256>>>();
    // 5) W-branch p@V + fused combine -> out
    out_w_kernel<<<dim3(CC/128, BB*128), 256>>>(x, gamma, out);
}